// round 4
// baseline (speedup 1.0000x reference)
#include <cuda_runtime.h>
#include <cuda_bf16.h>

// Problem constants
#define MAXN 100000
#define MAXE 1600000

typedef unsigned long long ull;

// ---------------- scratch (device globals — no runtime allocation) ----------
__device__ int   g_is64;            // 1 if ei_feat is int64, 0 if int32
__device__ int   g_cnt[MAXN];
__device__ float g_dinv[MAXN];
__device__ int   g_off[MAXN + 1];
__device__ int   g_cur[MAXN];
__device__ int   g_csr[MAXE];
__device__ int   g_bsum[256];
__device__ int   g_bscan[256];
__device__ float g_Xs[MAXN * 64];   // dinv[n] * X[n]
__device__ float g_Xt[MAXN * 64];   // aggregated layer-1 input
__device__ float g_H [MAXN * 256];  // elu(Xt @ Wblk + b)
__device__ float g_Fp[MAXN * 64];   // dinv[n] * (H @ W_fuse)

// ---------------- helpers ---------------------------------------------------
__device__ __forceinline__ void add4(float4& a, const float4 b) {
    a.x += b.x; a.y += b.y; a.z += b.z; a.w += b.w;
}

__device__ __forceinline__ int clampN(int v, int N) {
    v = v < 0 ? 0 : v;
    return v >= N ? N - 1 : v;
}

__device__ __forceinline__ int edge_at(const void* ei, int idx) {
    if (g_is64) return (int)((const long long*)ei)[idx];
    return ((const int*)ei)[idx];
}

// packed f32x2 helpers (Blackwell sm_100+): FFMA2 doubles fp32 FMA throughput
__device__ __forceinline__ ull pk2(float x) {
    ull r;
    asm("mov.b64 %0, {%1, %1};" : "=l"(r) : "f"(x));
    return r;
}
__device__ __forceinline__ void ffma2(ull& d, ull a, ull b) {
    asm("fma.rn.f32x2 %0, %1, %2, %0;" : "+l"(d) : "l"(a), "l"(b));
}
__device__ __forceinline__ void unpk2(float& lo, float& hi, ull v) {
    asm("mov.b64 {%0, %1}, %2;" : "=f"(lo), "=f"(hi) : "l"(v));
}

__device__ __forceinline__ float elu1(float v) {
    return v > 0.f ? v : (__expf(v) - 1.0f);
}

// ---------------- dtype detection -------------------------------------------
__global__ void k_detect(const unsigned int* __restrict__ w, int E) {
    if (threadIdx.x == 0 && blockIdx.x == 0) g_is64 = 1;
    __syncthreads();
    int npairs = E < 1024 ? E : 1024;
    int i = threadIdx.x;
    if (i < npairs) {
        if (w[2 * i + 1] != 0u) atomicExch(&g_is64, 0);
    }
}

// ---------------- CSR build -------------------------------------------------
__global__ void k_zero_cnt(int N) {
    for (int i = blockIdx.x * blockDim.x + threadIdx.x; i < N;
         i += gridDim.x * blockDim.x)
        g_cnt[i] = 0;
}

__global__ void k_hist(const void* __restrict__ ei, int E, int N) {
    int e = blockIdx.x * blockDim.x + threadIdx.x;
    if (e < E) {
        int dst = clampN(edge_at(ei, E + e), N);
        atomicAdd(&g_cnt[dst], 1);
    }
}

__global__ void k_scan1(int N) {
    __shared__ int s[1024];
    int tid = threadIdx.x;
    int i = blockIdx.x * 1024 + tid;
    int v = (i < N) ? g_cnt[i] : 0;
    s[tid] = v;
    __syncthreads();
    for (int o = 1; o < 1024; o <<= 1) {
        int t = (tid >= o) ? s[tid - o] : 0;
        __syncthreads();
        s[tid] += t;
        __syncthreads();
    }
    if (i < N) {
        g_off[i] = s[tid] - v;
        g_dinv[i] = rsqrtf((float)(v + 1));
    }
    if (tid == 1023) g_bsum[blockIdx.x] = s[1023];
}

__global__ void k_scan2(int NB) {
    __shared__ int s[128];
    int tid = threadIdx.x;
    int v = (tid < NB) ? g_bsum[tid] : 0;
    s[tid] = v;
    __syncthreads();
    for (int o = 1; o < 128; o <<= 1) {
        int t = (tid >= o) ? s[tid - o] : 0;
        __syncthreads();
        s[tid] += t;
        __syncthreads();
    }
    if (tid < NB) g_bscan[tid] = s[tid] - v;
}

__global__ void k_scan3(int N, int E) {
    int i = blockIdx.x * 1024 + threadIdx.x;
    if (i < N) {
        int v = g_off[i] + g_bscan[blockIdx.x];
        g_off[i] = v;
        g_cur[i] = v;
    }
    if (i == 0) g_off[N] = E;
}

__global__ void k_fill(const void* __restrict__ ei, int E, int N) {
    int e = blockIdx.x * blockDim.x + threadIdx.x;
    if (e < E) {
        int dst = clampN(edge_at(ei, E + e), N);
        int src = clampN(edge_at(ei, e), N);
        int pos = atomicAdd(&g_cur[dst], 1);
        if (pos < MAXE) g_csr[pos] = src;
    }
}

// ---------------- feature prep: Xs = dinv[n] * X[n] -------------------------
__global__ void k_prep(const float* __restrict__ X, int N) {
    int idx = blockIdx.x * blockDim.x + threadIdx.x;
    int total = N * 16;
    if (idx < total) {
        int n = idx >> 4;
        float s = g_dinv[n];
        float4 v = ((const float4*)X)[idx];
        v.x *= s; v.y *= s; v.z *= s; v.w *= s;
        ((float4*)g_Xs)[idx] = v;
    }
}

// ---------------- aggregation: g_Xt[n] = dinv[n]*(g_Xs[n] + sum_neigh g_Xs) -
__global__ void k_agg64(int N) {
    int tid = threadIdx.x;
    int lane = tid & 15;
    int n = blockIdx.x * 16 + (tid >> 4);
    if (n >= N) return;
    const float4* feat = (const float4*)g_Xs;
    int base = n * 16;
    float4 acc = feat[base + lane];
    int beg = g_off[n], end = g_off[n + 1];
    int j = beg;
    for (; j + 4 <= end; j += 4) {
        int u0 = g_csr[j];
        int u1 = g_csr[j + 1];
        int u2 = g_csr[j + 2];
        int u3 = g_csr[j + 3];
        float4 a = feat[u0 * 16 + lane];
        float4 b = feat[u1 * 16 + lane];
        float4 c = feat[u2 * 16 + lane];
        float4 d = feat[u3 * 16 + lane];
        add4(acc, a); add4(acc, b); add4(acc, c); add4(acc, d);
    }
    for (; j < end; ++j) {
        int u = g_csr[j];
        add4(acc, feat[u * 16 + lane]);
    }
    float s = g_dinv[n];
    acc.x *= s; acc.y *= s; acc.z *= s; acc.w *= s;
    ((float4*)g_Xt)[base + lane] = acc;
}

// ---------------- GEMM1: H = elu(Xt @ blockdiag(Wn,Ws) + b) -----------------
// 1024 threads = 32 warps; block covers 32 nodes x 256 cols.
// lane = node, warp = 8 output cols -> weight LDS is warp-uniform (broadcast).
// x (K=32) in registers; FFMA2 packed fp32 math.
__global__ __launch_bounds__(1024, 1)
void k_gemm1(const float* __restrict__ Wn, const float* __restrict__ bn,
             const float* __restrict__ Ws, const float* __restrict__ bs,
             int N) {
    __shared__ __align__(16) float sW[8192];   // [0:4096)=Wn (k*128+j), [4096:)=Ws
    __shared__ float sX[32][65];               // padded: conflict-free column reads
    __shared__ float sB[256];
    int tid = threadIdx.x;
    for (int i = tid; i < 4096; i += 1024) {
        sW[i]        = Wn[i];
        sW[4096 + i] = Ws[i];
    }
    if (tid < 256) sB[tid] = (tid < 128) ? bn[tid] : bs[tid - 128];
    int node0 = blockIdx.x * 32;
    for (int i = tid; i < 2048; i += 1024) {
        int r = i >> 6, c = i & 63;
        int n = node0 + r;
        sX[r][c] = (n < N) ? g_Xt[n * 64 + c] : 0.0f;
    }
    __syncthreads();

    int ww = tid >> 5, lane = tid & 31;
    int c0 = ww * 8;                 // global col base of this warp
    int hsel = ww >> 4;              // 0 = nuc half, 1 = surf half
    int j0 = (ww & 15) * 8;          // local col within 128

    float x[32];
#pragma unroll
    for (int k = 0; k < 32; ++k) x[k] = sX[lane][hsel * 32 + k];

    ull acc0 = 0, acc1 = 0, acc2 = 0, acc3 = 0;   // {0.f,0.f} pairs
    const float* wb = &sW[hsel * 4096 + j0];
#pragma unroll
    for (int k = 0; k < 32; ++k) {
        ull a = pk2(x[k]);
        ulonglong2 w01 = *(const ulonglong2*)&wb[k * 128];      // cols j0..j0+3
        ulonglong2 w23 = *(const ulonglong2*)&wb[k * 128 + 4];  // cols j0+4..j0+7
        ffma2(acc0, a, w01.x);
        ffma2(acc1, a, w01.y);
        ffma2(acc2, a, w23.x);
        ffma2(acc3, a, w23.y);
    }

    int n = node0 + lane;
    if (n < N) {
        float o[8];
        unpk2(o[0], o[1], acc0);
        unpk2(o[2], o[3], acc1);
        unpk2(o[4], o[5], acc2);
        unpk2(o[6], o[7], acc3);
        float4 r0, r1;
        r0.x = elu1(o[0] + sB[c0 + 0]);
        r0.y = elu1(o[1] + sB[c0 + 1]);
        r0.z = elu1(o[2] + sB[c0 + 2]);
        r0.w = elu1(o[3] + sB[c0 + 3]);
        r1.x = elu1(o[4] + sB[c0 + 4]);
        r1.y = elu1(o[5] + sB[c0 + 5]);
        r1.z = elu1(o[6] + sB[c0 + 6]);
        r1.w = elu1(o[7] + sB[c0 + 7]);
        *(float4*)&g_H[n * 256 + c0]     = r0;
        *(float4*)&g_H[n * 256 + c0 + 4] = r1;
    }
}

// ---------------- GEMM2: Fp = dinv * (H @ W_fuse) ---------------------------
// 256 threads = 8 warps; block covers 32 nodes x 64 cols; K=256 chunked by 64.
// lane = node, warp = 8 cols; uniform weight loads; FFMA2.
__global__ void k_gemm2(const float* __restrict__ Wf, int N) {
    __shared__ float sH[32][65];
    __shared__ __align__(16) float sW2[64][64];
    int tid = threadIdx.x;
    int ww = tid >> 5, lane = tid & 31;
    int node0 = blockIdx.x * 32;
    int j0 = ww * 8;

    ull acc0 = 0, acc1 = 0, acc2 = 0, acc3 = 0;

    for (int kc = 0; kc < 4; ++kc) {
        for (int i = tid; i < 512; i += 256) {
            int r = i >> 4, cq = i & 15;
            float4 v = {0.f, 0.f, 0.f, 0.f};
            int n = node0 + r;
            if (n < N)
                v = *(const float4*)&g_H[n * 256 + kc * 64 + cq * 4];
            sH[r][cq * 4 + 0] = v.x;
            sH[r][cq * 4 + 1] = v.y;
            sH[r][cq * 4 + 2] = v.z;
            sH[r][cq * 4 + 3] = v.w;
        }
        for (int i = tid; i < 1024; i += 256) {
            int r = i >> 4, cq = i & 15;
            *(float4*)&sW2[r][cq * 4] = *(const float4*)&Wf[(kc * 64 + r) * 64 + cq * 4];
        }
        __syncthreads();
#pragma unroll
        for (int k = 0; k < 64; ++k) {
            ull a = pk2(sH[lane][k]);
            ulonglong2 w01 = *(const ulonglong2*)&sW2[k][j0];
            ulonglong2 w23 = *(const ulonglong2*)&sW2[k][j0 + 4];
            ffma2(acc0, a, w01.x);
            ffma2(acc1, a, w01.y);
            ffma2(acc2, a, w23.x);
            ffma2(acc3, a, w23.y);
        }
        __syncthreads();
    }

    int n = node0 + lane;
    if (n < N) {
        float s = g_dinv[n];
        float o[8];
        unpk2(o[0], o[1], acc0);
        unpk2(o[2], o[3], acc1);
        unpk2(o[4], o[5], acc2);
        unpk2(o[6], o[7], acc3);
        float4 r0 = {o[0] * s, o[1] * s, o[2] * s, o[3] * s};
        float4 r1 = {o[4] * s, o[5] * s, o[6] * s, o[7] * s};
        *(float4*)&g_Fp[n * 64 + j0]     = r0;
        *(float4*)&g_Fp[n * 64 + j0 + 4] = r1;
    }
}

// ---------------- layer-2 aggregation + bias + softmax ----------------------
__global__ void k_agg_softmax(const float* __restrict__ bf, float* __restrict__ out, int N) {
    int tid = threadIdx.x;
    int lane = tid & 15;
    int n = blockIdx.x * 16 + (tid >> 4);
    if (n >= N) return;
    const float4* feat = (const float4*)g_Fp;
    int base = n * 16;
    float4 acc = feat[base + lane];
    int beg = g_off[n], end = g_off[n + 1];
    int j = beg;
    for (; j + 4 <= end; j += 4) {
        int u0 = g_csr[j];
        int u1 = g_csr[j + 1];
        int u2 = g_csr[j + 2];
        int u3 = g_csr[j + 3];
        float4 a = feat[u0 * 16 + lane];
        float4 b = feat[u1 * 16 + lane];
        float4 c = feat[u2 * 16 + lane];
        float4 d = feat[u3 * 16 + lane];
        add4(acc, a); add4(acc, b); add4(acc, c); add4(acc, d);
    }
    for (; j < end; ++j) {
        int u = g_csr[j];
        add4(acc, feat[u * 16 + lane]);
    }
    float s = g_dinv[n];
    float4 b4 = ((const float4*)bf)[lane];
    float4 z = {acc.x * s + b4.x, acc.y * s + b4.y,
                acc.z * s + b4.z, acc.w * s + b4.w};

    float m = fmaxf(fmaxf(z.x, z.y), fmaxf(z.z, z.w));
#pragma unroll
    for (int o = 8; o > 0; o >>= 1)
        m = fmaxf(m, __shfl_xor_sync(0xffffffffu, m, o, 16));
    z.x = __expf(z.x - m); z.y = __expf(z.y - m);
    z.z = __expf(z.z - m); z.w = __expf(z.w - m);
    float sum = z.x + z.y + z.z + z.w;
#pragma unroll
    for (int o = 8; o > 0; o >>= 1)
        sum += __shfl_xor_sync(0xffffffffu, sum, o, 16);
    float inv = 1.0f / sum;
    z.x *= inv; z.y *= inv; z.z *= inv; z.w *= inv;
    ((float4*)out)[base + lane] = z;
}

// ---------------- launch ----------------------------------------------------
extern "C" void kernel_launch(void* const* d_in, const int* in_sizes, int n_in,
                              void* d_out, int out_size) {
    const float* X  = (const float*)d_in[0];
    const void*  ei = d_in[1];            // int32 or int64 — detected on device
    const float* Wn = (const float*)d_in[3];
    const float* bn = (const float*)d_in[4];
    const float* Ws = (const float*)d_in[5];
    const float* bs = (const float*)d_in[6];
    const float* Wf = (const float*)d_in[7];
    const float* bf = (const float*)d_in[8];
    float* out = (float*)d_out;

    int N = in_sizes[0] / 64;
    int E = in_sizes[1] / 2;
    int NB = (N + 1023) / 1024;
    int NB32 = (N + 31) / 32;

    k_detect<<<1, 1024>>>((const unsigned int*)ei, E);
    k_zero_cnt<<<256, 256>>>(N);
    k_hist<<<(E + 511) / 512, 512>>>(ei, E, N);
    k_scan1<<<NB, 1024>>>(N);
    k_scan2<<<1, 128>>>(NB);
    k_scan3<<<NB, 1024>>>(N, E);
    k_fill<<<(E + 511) / 512, 512>>>(ei, E, N);
    k_prep<<<(N * 16 + 255) / 256, 256>>>(X, N);
    k_agg64<<<(N + 15) / 16, 256>>>(N);
    k_gemm1<<<NB32, 1024>>>(Wn, bn, Ws, bs, N);
    k_gemm2<<<NB32, 256>>>(Wf, N);
    k_agg_softmax<<<(N + 15) / 16, 256>>>(bf, out, N);
}

// round 5
// speedup vs baseline: 1.5666x; 1.5666x over previous
#include <cuda_runtime.h>
#include <cuda_bf16.h>

// Problem constants
#define MAXN 100000
#define MAXE 1600000

typedef unsigned long long ull;

// ---------------- scratch (device globals — no runtime allocation) ----------
__device__ int   g_is64;            // 1 if ei_feat is int64, 0 if int32
__device__ int   g_cnt[MAXN];
__device__ float g_dinv[MAXN];
__device__ int   g_off[MAXN + 1];
__device__ int   g_cur[MAXN];
__device__ int   g_csr[MAXE];
__device__ int   g_bsum[256];
__device__ int   g_bscan[256];
__device__ float g_Xs[MAXN * 64];   // dinv[n] * X[n]
__device__ float g_Xt[MAXN * 64];   // aggregated layer-1 input
__device__ float g_H [MAXN * 256];  // elu(Xt @ Wblk + b)
__device__ float g_Fp[MAXN * 64];   // dinv[n] * (H @ W_fuse)

// ---------------- helpers ---------------------------------------------------
__device__ __forceinline__ void add4(float4& a, const float4 b) {
    a.x += b.x; a.y += b.y; a.z += b.z; a.w += b.w;
}

__device__ __forceinline__ int clampN(int v, int N) {
    v = v < 0 ? 0 : v;
    return v >= N ? N - 1 : v;
}

__device__ __forceinline__ int edge_at(const void* ei, int idx) {
    if (g_is64) return (int)((const long long*)ei)[idx];
    return ((const int*)ei)[idx];
}

// packed f32x2 helpers (Blackwell sm_100+): FFMA2 doubles fp32 FMA throughput
__device__ __forceinline__ ull pk2(float x) {
    ull r;
    asm("mov.b64 %0, {%1, %1};" : "=l"(r) : "f"(x));
    return r;
}
__device__ __forceinline__ void ffma2(ull& d, ull a, ull b) {
    asm("fma.rn.f32x2 %0, %1, %2, %0;" : "+l"(d) : "l"(a), "l"(b));
}
__device__ __forceinline__ void unpk2(float& lo, float& hi, ull v) {
    asm("mov.b64 {%0, %1}, %2;" : "=f"(lo), "=f"(hi) : "l"(v));
}

__device__ __forceinline__ float elu1(float v) {
    return v > 0.f ? v : (__expf(v) - 1.0f);
}

// ---------------- dtype detection -------------------------------------------
__global__ void k_detect(const unsigned int* __restrict__ w, int E) {
    if (threadIdx.x == 0 && blockIdx.x == 0) g_is64 = 1;
    __syncthreads();
    int npairs = E < 1024 ? E : 1024;
    int i = threadIdx.x;
    if (i < npairs) {
        if (w[2 * i + 1] != 0u) atomicExch(&g_is64, 0);
    }
}

// ---------------- CSR build -------------------------------------------------
__global__ void k_zero_cnt(int N) {
    for (int i = blockIdx.x * blockDim.x + threadIdx.x; i < N;
         i += gridDim.x * blockDim.x)
        g_cnt[i] = 0;
}

__global__ void k_hist(const void* __restrict__ ei, int E, int N) {
    int e = blockIdx.x * blockDim.x + threadIdx.x;
    if (e < E) {
        int dst = clampN(edge_at(ei, E + e), N);
        atomicAdd(&g_cnt[dst], 1);
    }
}

__global__ void k_scan1(int N) {
    __shared__ int s[1024];
    int tid = threadIdx.x;
    int i = blockIdx.x * 1024 + tid;
    int v = (i < N) ? g_cnt[i] : 0;
    s[tid] = v;
    __syncthreads();
    for (int o = 1; o < 1024; o <<= 1) {
        int t = (tid >= o) ? s[tid - o] : 0;
        __syncthreads();
        s[tid] += t;
        __syncthreads();
    }
    if (i < N) {
        g_off[i] = s[tid] - v;
        g_dinv[i] = rsqrtf((float)(v + 1));
    }
    if (tid == 1023) g_bsum[blockIdx.x] = s[1023];
}

__global__ void k_scan2(int NB) {
    __shared__ int s[128];
    int tid = threadIdx.x;
    int v = (tid < NB) ? g_bsum[tid] : 0;
    s[tid] = v;
    __syncthreads();
    for (int o = 1; o < 128; o <<= 1) {
        int t = (tid >= o) ? s[tid - o] : 0;
        __syncthreads();
        s[tid] += t;
        __syncthreads();
    }
    if (tid < NB) g_bscan[tid] = s[tid] - v;
}

__global__ void k_scan3(int N, int E) {
    int i = blockIdx.x * 1024 + threadIdx.x;
    if (i < N) {
        int v = g_off[i] + g_bscan[blockIdx.x];
        g_off[i] = v;
        g_cur[i] = v;
    }
    if (i == 0) g_off[N] = E;
}

__global__ void k_fill(const void* __restrict__ ei, int E, int N) {
    int e = blockIdx.x * blockDim.x + threadIdx.x;
    if (e < E) {
        int dst = clampN(edge_at(ei, E + e), N);
        int src = clampN(edge_at(ei, e), N);
        int pos = atomicAdd(&g_cur[dst], 1);
        if (pos < MAXE) g_csr[pos] = src;
    }
}

// ---------------- feature prep: Xs = dinv[n] * X[n] -------------------------
__global__ void k_prep(const float* __restrict__ X, int N) {
    int idx = blockIdx.x * blockDim.x + threadIdx.x;
    int total = N * 16;
    if (idx < total) {
        int n = idx >> 4;
        float s = g_dinv[n];
        float4 v = ((const float4*)X)[idx];
        v.x *= s; v.y *= s; v.z *= s; v.w *= s;
        ((float4*)g_Xs)[idx] = v;
    }
}

// ---------------- aggregation: g_Xt[n] = dinv[n]*(g_Xs[n] + sum_neigh g_Xs) -
__global__ void k_agg64(int N) {
    int tid = threadIdx.x;
    int lane = tid & 15;
    int n = blockIdx.x * 16 + (tid >> 4);
    if (n >= N) return;
    const float4* feat = (const float4*)g_Xs;
    int base = n * 16;
    float4 acc = feat[base + lane];
    int beg = g_off[n], end = g_off[n + 1];
    int j = beg;
    for (; j + 4 <= end; j += 4) {
        int u0 = g_csr[j];
        int u1 = g_csr[j + 1];
        int u2 = g_csr[j + 2];
        int u3 = g_csr[j + 3];
        float4 a = feat[u0 * 16 + lane];
        float4 b = feat[u1 * 16 + lane];
        float4 c = feat[u2 * 16 + lane];
        float4 d = feat[u3 * 16 + lane];
        add4(acc, a); add4(acc, b); add4(acc, c); add4(acc, d);
    }
    for (; j < end; ++j) {
        int u = g_csr[j];
        add4(acc, feat[u * 16 + lane]);
    }
    float s = g_dinv[n];
    acc.x *= s; acc.y *= s; acc.z *= s; acc.w *= s;
    ((float4*)g_Xt)[base + lane] = acc;
}

// ---------------- GEMM1: H = elu(Xt @ blockdiag(Wn,Ws) + b) -----------------
// 256 threads = 8 warps; block covers 32 nodes x 256 cols.
// lane = node; warp ww owns 32 contiguous cols (uniform/broadcast weight LDS).
// x (K=32) in registers; 16 packed f32x2 accumulators; no spills at <=255 regs.
__global__ __launch_bounds__(256)
void k_gemm1(const float* __restrict__ Wn, const float* __restrict__ bn,
             const float* __restrict__ Ws, const float* __restrict__ bs,
             int N) {
    __shared__ __align__(16) float sW[8192];   // [0:4096)=Wn (k*128+j), [4096:)=Ws
    __shared__ float sX[32][65];               // padded: conflict-free column reads
    __shared__ float sB[256];
    int tid = threadIdx.x;
    for (int i = tid; i < 4096; i += 256) {
        sW[i]        = Wn[i];
        sW[4096 + i] = Ws[i];
    }
    if (tid < 256) sB[tid] = (tid < 128) ? bn[tid] : bs[tid - 128];
    int node0 = blockIdx.x * 32;
    for (int i = tid; i < 2048; i += 256) {
        int r = i >> 6, c = i & 63;
        int n = node0 + r;
        sX[r][c] = (n < N) ? g_Xt[n * 64 + c] : 0.0f;
    }
    __syncthreads();

    int ww = tid >> 5, lane = tid & 31;
    int hsel = ww >> 2;              // warps 0-3: nuc cols, 4-7: surf cols
    int j0 = (ww & 3) * 32;          // local col within 128
    int c0 = hsel * 128 + j0;        // global col base (32 cols per warp)

    float x[32];
#pragma unroll
    for (int k = 0; k < 32; ++k) x[k] = sX[lane][hsel * 32 + k];

    ull acc[16];
#pragma unroll
    for (int i = 0; i < 16; ++i) acc[i] = 0ull;

    const float* wb = &sW[hsel * 4096 + j0];
#pragma unroll
    for (int k = 0; k < 32; ++k) {
        ull a = pk2(x[k]);
        const ulonglong2* wp = (const ulonglong2*)&wb[k * 128];
#pragma unroll
        for (int i = 0; i < 8; ++i) {
            ulonglong2 w = wp[i];
            ffma2(acc[2 * i],     a, w.x);
            ffma2(acc[2 * i + 1], a, w.y);
        }
    }

    int n = node0 + lane;
    if (n < N) {
#pragma unroll
        for (int i = 0; i < 8; ++i) {
            float o0, o1, o2, o3;
            unpk2(o0, o1, acc[2 * i]);
            unpk2(o2, o3, acc[2 * i + 1]);
            float4 r;
            r.x = elu1(o0 + sB[c0 + 4 * i + 0]);
            r.y = elu1(o1 + sB[c0 + 4 * i + 1]);
            r.z = elu1(o2 + sB[c0 + 4 * i + 2]);
            r.w = elu1(o3 + sB[c0 + 4 * i + 3]);
            *(float4*)&g_H[n * 256 + c0 + 4 * i] = r;
        }
    }
}

// ---------------- GEMM2: Fp = dinv * (H @ W_fuse) ---------------------------
// 256 threads = 8 warps; block covers 32 nodes x 64 cols; K=256 chunked by 64.
// lane = node, warp = 8 cols; uniform weight loads; FFMA2.
__global__ __launch_bounds__(256)
void k_gemm2(const float* __restrict__ Wf, int N) {
    __shared__ float sH[32][65];
    __shared__ __align__(16) float sW2[64][64];
    int tid = threadIdx.x;
    int ww = tid >> 5, lane = tid & 31;
    int node0 = blockIdx.x * 32;
    int j0 = ww * 8;

    ull acc0 = 0, acc1 = 0, acc2 = 0, acc3 = 0;

    for (int kc = 0; kc < 4; ++kc) {
        for (int i = tid; i < 512; i += 256) {
            int r = i >> 4, cq = i & 15;
            float4 v = {0.f, 0.f, 0.f, 0.f};
            int n = node0 + r;
            if (n < N)
                v = *(const float4*)&g_H[n * 256 + kc * 64 + cq * 4];
            sH[r][cq * 4 + 0] = v.x;
            sH[r][cq * 4 + 1] = v.y;
            sH[r][cq * 4 + 2] = v.z;
            sH[r][cq * 4 + 3] = v.w;
        }
        for (int i = tid; i < 1024; i += 256) {
            int r = i >> 4, cq = i & 15;
            *(float4*)&sW2[r][cq * 4] = *(const float4*)&Wf[(kc * 64 + r) * 64 + cq * 4];
        }
        __syncthreads();
#pragma unroll
        for (int k = 0; k < 64; ++k) {
            ull a = pk2(sH[lane][k]);
            ulonglong2 w01 = *(const ulonglong2*)&sW2[k][j0];
            ulonglong2 w23 = *(const ulonglong2*)&sW2[k][j0 + 4];
            ffma2(acc0, a, w01.x);
            ffma2(acc1, a, w01.y);
            ffma2(acc2, a, w23.x);
            ffma2(acc3, a, w23.y);
        }
        __syncthreads();
    }

    int n = node0 + lane;
    if (n < N) {
        float s = g_dinv[n];
        float o[8];
        unpk2(o[0], o[1], acc0);
        unpk2(o[2], o[3], acc1);
        unpk2(o[4], o[5], acc2);
        unpk2(o[6], o[7], acc3);
        float4 r0 = {o[0] * s, o[1] * s, o[2] * s, o[3] * s};
        float4 r1 = {o[4] * s, o[5] * s, o[6] * s, o[7] * s};
        *(float4*)&g_Fp[n * 64 + j0]     = r0;
        *(float4*)&g_Fp[n * 64 + j0 + 4] = r1;
    }
}

// ---------------- layer-2 aggregation + bias + softmax ----------------------
__global__ void k_agg_softmax(const float* __restrict__ bf, float* __restrict__ out, int N) {
    int tid = threadIdx.x;
    int lane = tid & 15;
    int n = blockIdx.x * 16 + (tid >> 4);
    if (n >= N) return;
    const float4* feat = (const float4*)g_Fp;
    int base = n * 16;
    float4 acc = feat[base + lane];
    int beg = g_off[n], end = g_off[n + 1];
    int j = beg;
    for (; j + 4 <= end; j += 4) {
        int u0 = g_csr[j];
        int u1 = g_csr[j + 1];
        int u2 = g_csr[j + 2];
        int u3 = g_csr[j + 3];
        float4 a = feat[u0 * 16 + lane];
        float4 b = feat[u1 * 16 + lane];
        float4 c = feat[u2 * 16 + lane];
        float4 d = feat[u3 * 16 + lane];
        add4(acc, a); add4(acc, b); add4(acc, c); add4(acc, d);
    }
    for (; j < end; ++j) {
        int u = g_csr[j];
        add4(acc, feat[u * 16 + lane]);
    }
    float s = g_dinv[n];
    float4 b4 = ((const float4*)bf)[lane];
    float4 z = {acc.x * s + b4.x, acc.y * s + b4.y,
                acc.z * s + b4.z, acc.w * s + b4.w};

    float m = fmaxf(fmaxf(z.x, z.y), fmaxf(z.z, z.w));
#pragma unroll
    for (int o = 8; o > 0; o >>= 1)
        m = fmaxf(m, __shfl_xor_sync(0xffffffffu, m, o, 16));
    z.x = __expf(z.x - m); z.y = __expf(z.y - m);
    z.z = __expf(z.z - m); z.w = __expf(z.w - m);
    float sum = z.x + z.y + z.z + z.w;
#pragma unroll
    for (int o = 8; o > 0; o >>= 1)
        sum += __shfl_xor_sync(0xffffffffu, sum, o, 16);
    float inv = 1.0f / sum;
    z.x *= inv; z.y *= inv; z.z *= inv; z.w *= inv;
    ((float4*)out)[base + lane] = z;
}

// ---------------- launch ----------------------------------------------------
extern "C" void kernel_launch(void* const* d_in, const int* in_sizes, int n_in,
                              void* d_out, int out_size) {
    const float* X  = (const float*)d_in[0];
    const void*  ei = d_in[1];            // int32 or int64 — detected on device
    const float* Wn = (const float*)d_in[3];
    const float* bn = (const float*)d_in[4];
    const float* Ws = (const float*)d_in[5];
    const float* bs = (const float*)d_in[6];
    const float* Wf = (const float*)d_in[7];
    const float* bf = (const float*)d_in[8];
    float* out = (float*)d_out;

    int N = in_sizes[0] / 64;
    int E = in_sizes[1] / 2;
    int NB = (N + 1023) / 1024;
    int NB32 = (N + 31) / 32;

    k_detect<<<1, 1024>>>((const unsigned int*)ei, E);
    k_zero_cnt<<<256, 256>>>(N);
    k_hist<<<(E + 511) / 512, 512>>>(ei, E, N);
    k_scan1<<<NB, 1024>>>(N);
    k_scan2<<<1, 128>>>(NB);
    k_scan3<<<NB, 1024>>>(N, E);
    k_fill<<<(E + 511) / 512, 512>>>(ei, E, N);
    k_prep<<<(N * 16 + 255) / 256, 256>>>(X, N);
    k_agg64<<<(N + 15) / 16, 256>>>(N);
    k_gemm1<<<NB32, 256>>>(Wn, bn, Ws, bs, N);
    k_gemm2<<<NB32, 256>>>(Wf, N);
    k_agg_softmax<<<(N + 15) / 16, 256>>>(bf, out, N);
}

// round 6
// speedup vs baseline: 2.0279x; 1.2945x over previous
#include <cuda_runtime.h>
#include <cuda_bf16.h>

// Problem constants
#define MAXN 100000
#define MAXE 1600000

typedef unsigned long long ull;

// ---------------- scratch (device globals — no runtime allocation) ----------
__device__ int   g_is64;            // 1 if ei_feat is int64, 0 if int32
__device__ int   g_cnt[MAXN];
__device__ float g_dinv[MAXN];
__device__ int   g_off[MAXN + 1];
__device__ int   g_cur[MAXN];
__device__ int   g_csr[MAXE];
__device__ int   g_bsum[256];
__device__ int   g_bscan[256];
__device__ float g_Xt[MAXN * 64];   // aggregated layer-1 input
__device__ float g_Fp[MAXN * 64];   // dinv[n] * (H @ W_fuse)

// ---------------- helpers ---------------------------------------------------
__device__ __forceinline__ int clampN(int v, int N) {
    v = v < 0 ? 0 : v;
    return v >= N ? N - 1 : v;
}

__device__ __forceinline__ int edge_at(const void* ei, int idx) {
    if (g_is64) return (int)((const long long*)ei)[idx];
    return ((const int*)ei)[idx];
}

// packed f32x2 helpers (Blackwell sm_100+): FFMA2 doubles fp32 FMA throughput
__device__ __forceinline__ ull pk2(float x) {
    ull r;
    asm("mov.b64 %0, {%1, %1};" : "=l"(r) : "f"(x));
    return r;
}
__device__ __forceinline__ void ffma2(ull& d, ull a, ull b) {
    asm("fma.rn.f32x2 %0, %1, %2, %0;" : "+l"(d) : "l"(a), "l"(b));
}
__device__ __forceinline__ void unpk2(float& lo, float& hi, ull v) {
    asm("mov.b64 {%0, %1}, %2;" : "=f"(lo), "=f"(hi) : "l"(v));
}

__device__ __forceinline__ float elu1(float v) {
    return v > 0.f ? v : (__expf(v) - 1.0f);
}

// ---------------- dtype detection -------------------------------------------
__global__ void k_detect(const unsigned int* __restrict__ w, int E) {
    if (threadIdx.x == 0 && blockIdx.x == 0) g_is64 = 1;
    __syncthreads();
    int npairs = E < 1024 ? E : 1024;
    int i = threadIdx.x;
    if (i < npairs) {
        if (w[2 * i + 1] != 0u) atomicExch(&g_is64, 0);
    }
}

// ---------------- CSR build -------------------------------------------------
__global__ void k_zero_cnt(int N) {
    for (int i = blockIdx.x * blockDim.x + threadIdx.x; i < N;
         i += gridDim.x * blockDim.x)
        g_cnt[i] = 0;
}

__global__ void k_hist(const void* __restrict__ ei, int E, int N) {
    int e = blockIdx.x * blockDim.x + threadIdx.x;
    if (e < E) {
        int dst = clampN(edge_at(ei, E + e), N);
        atomicAdd(&g_cnt[dst], 1);
    }
}

__global__ void k_scan1(int N) {
    __shared__ int s[1024];
    int tid = threadIdx.x;
    int i = blockIdx.x * 1024 + tid;
    int v = (i < N) ? g_cnt[i] : 0;
    s[tid] = v;
    __syncthreads();
    for (int o = 1; o < 1024; o <<= 1) {
        int t = (tid >= o) ? s[tid - o] : 0;
        __syncthreads();
        s[tid] += t;
        __syncthreads();
    }
    if (i < N) {
        g_off[i] = s[tid] - v;
        g_dinv[i] = rsqrtf((float)(v + 1));
    }
    if (tid == 1023) g_bsum[blockIdx.x] = s[1023];
}

__global__ void k_scan2(int NB) {
    __shared__ int s[128];
    int tid = threadIdx.x;
    int v = (tid < NB) ? g_bsum[tid] : 0;
    s[tid] = v;
    __syncthreads();
    for (int o = 1; o < 128; o <<= 1) {
        int t = (tid >= o) ? s[tid - o] : 0;
        __syncthreads();
        s[tid] += t;
        __syncthreads();
    }
    if (tid < NB) g_bscan[tid] = s[tid] - v;
}

__global__ void k_scan3(int N, int E) {
    int i = blockIdx.x * 1024 + threadIdx.x;
    if (i < N) {
        int v = g_off[i] + g_bscan[blockIdx.x];
        g_off[i] = v;
        g_cur[i] = v;
    }
    if (i == 0) g_off[N] = E;
}

__global__ void k_fill(const void* __restrict__ ei, int E, int N) {
    int e = blockIdx.x * blockDim.x + threadIdx.x;
    if (e < E) {
        int dst = clampN(edge_at(ei, E + e), N);
        int src = clampN(edge_at(ei, e), N);
        int pos = atomicAdd(&g_cur[dst], 1);
        if (pos < MAXE) g_csr[pos] = src;
    }
}

// ---------------- layer-1 aggregation (prep fused) ---------------------------
// g_Xt[n] = dinv[n] * ( dinv[n]*X[n] + sum_u dinv[u]*X[u] )
// 16 lanes per node, each lane owns one float4 of the 64-wide row.
__global__ void k_agg64(const float* __restrict__ X, int N) {
    int tid = threadIdx.x;
    int lane = tid & 15;
    int n = blockIdx.x * 16 + (tid >> 4);
    if (n >= N) return;
    const float4* feat = (const float4*)X;
    float dn = g_dinv[n];
    float4 self = feat[n * 16 + lane];
    float4 acc = {self.x * dn, self.y * dn, self.z * dn, self.w * dn};
    int beg = g_off[n], end = g_off[n + 1];
    int j = beg;
    for (; j + 8 <= end; j += 8) {
        int u[8];
#pragma unroll
        for (int t = 0; t < 8; ++t) u[t] = g_csr[j + t];
        float du[8]; float4 v[8];
#pragma unroll
        for (int t = 0; t < 8; ++t) { du[t] = g_dinv[u[t]]; v[t] = feat[u[t] * 16 + lane]; }
#pragma unroll
        for (int t = 0; t < 8; ++t) {
            acc.x += du[t] * v[t].x; acc.y += du[t] * v[t].y;
            acc.z += du[t] * v[t].z; acc.w += du[t] * v[t].w;
        }
    }
    for (; j < end; ++j) {
        int u = g_csr[j];
        float du = g_dinv[u];
        float4 v = feat[u * 16 + lane];
        acc.x += du * v.x; acc.y += du * v.y;
        acc.z += du * v.z; acc.w += du * v.w;
    }
    acc.x *= dn; acc.y *= dn; acc.z *= dn; acc.w *= dn;
    ((float4*)g_Xt)[n * 16 + lane] = acc;
}

// ---------------- fused MLP: Fp = dinv * (elu(Xt@Wblk+b) @ Wf) --------------
// Block = 64 nodes, 256 threads, dynamic smem:
//   sHT[256][68]  H transposed (col-major)  17408 floats
//   sW [8192]     Wn+Ws, then reused for Wf k-chunks
//   sB [256]      bias
// Phase A (GEMM1): warp ww -> 32 cols (hsel=ww>>2, j0=(ww&3)*32), lane = node,
//   two node-halves; x in regs; 16 packed accumulators; writes sHT (STS.32,
//   lanes->consecutive nodes: conflict-free).
// Phase B (GEMM2): thread = 4 nodes x 4 cols; per k: 1 LDS.128 (4 nodes' H),
//   1 LDS.128 (4 cols' Wf), 8 FFMA2 -> FFMA2-pipe bound.
#define SMEM_HT  17408
#define SMEM_W   (SMEM_HT)            // offset of sW
#define SMEM_B   (SMEM_HT + 8192)     // offset of sB
#define SMEM_FLOATS (SMEM_HT + 8192 + 256)

__global__ __launch_bounds__(256)
void k_mlp(const float* __restrict__ Wn, const float* __restrict__ bn,
           const float* __restrict__ Ws, const float* __restrict__ bs,
           const float* __restrict__ Wf, int N) {
    extern __shared__ float smem[];
    float* sHT = smem;
    float* sW  = smem + SMEM_W;
    float* sB  = smem + SMEM_B;

    int tid = threadIdx.x;
    int node0 = blockIdx.x * 64;

    // load Wn/Ws + bias
    for (int i = tid; i < 4096; i += 256) {
        sW[i]        = Wn[i];
        sW[4096 + i] = Ws[i];
    }
    sB[tid] = (tid < 128) ? bn[tid] : bs[tid - 128];
    __syncthreads();

    // ---------------- Phase A: H = elu(Xt @ blockdiag(Wn,Ws) + b) ----------
    {
        int ww = tid >> 5, lane = tid & 31;
        int hsel = ww >> 2;              // 0: nuc, 1: surf
        int j0 = (ww & 3) * 32;          // local col base within 128
        int c0 = hsel * 128 + j0;        // global col base (32 cols per warp)
        const float* wb = &sW[hsel * 4096 + j0];

        for (int nh = 0; nh < 2; ++nh) {
            int n = node0 + nh * 32 + lane;
            bool valid = n < N;
            float x[32];
            const float4* xp = (const float4*)&g_Xt[(valid ? n : 0) * 64 + hsel * 32];
#pragma unroll
            for (int q = 0; q < 8; ++q) {
                float4 v = valid ? xp[q] : make_float4(0.f, 0.f, 0.f, 0.f);
                x[4 * q + 0] = v.x; x[4 * q + 1] = v.y;
                x[4 * q + 2] = v.z; x[4 * q + 3] = v.w;
            }
            ull acc[16];
#pragma unroll
            for (int i = 0; i < 16; ++i) acc[i] = 0ull;
#pragma unroll
            for (int k = 0; k < 32; ++k) {
                ull a = pk2(x[k]);
                const ulonglong2* wp = (const ulonglong2*)&wb[k * 128];
#pragma unroll
                for (int i = 0; i < 8; ++i) {
                    ulonglong2 w = wp[i];
                    ffma2(acc[2 * i],     a, w.x);
                    ffma2(acc[2 * i + 1], a, w.y);
                }
            }
            int ncol = nh * 32 + lane;
#pragma unroll
            for (int i = 0; i < 8; ++i) {
                float o0, o1, o2, o3;
                unpk2(o0, o1, acc[2 * i]);
                unpk2(o2, o3, acc[2 * i + 1]);
                int c = c0 + 4 * i;
                sHT[(c + 0) * 68 + ncol] = elu1(o0 + sB[c + 0]);
                sHT[(c + 1) * 68 + ncol] = elu1(o1 + sB[c + 1]);
                sHT[(c + 2) * 68 + ncol] = elu1(o2 + sB[c + 2]);
                sHT[(c + 3) * 68 + ncol] = elu1(o3 + sB[c + 3]);
            }
        }
    }

    // ---------------- Phase B: Fp = dinv * (H @ Wf) -------------------------
    {
        int tx = tid & 15;   // col quad: cols tx*4..tx*4+3
        int ty = tid >> 4;   // node quad: nodes ty*4..ty*4+3
        ull acc[8];
#pragma unroll
        for (int i = 0; i < 8; ++i) acc[i] = 0ull;

        for (int kc = 0; kc < 2; ++kc) {
            __syncthreads();   // sW free (phase A done / previous chunk done)
            for (int i = tid; i < 2048; i += 256)
                ((float4*)sW)[i] = ((const float4*)Wf)[kc * 2048 + i];
            __syncthreads();
#pragma unroll 4
            for (int k = 0; k < 128; ++k) {
                int kk = kc * 128 + k;
                float4 xv = *(const float4*)&sHT[kk * 68 + ty * 4];
                ulonglong2 w = *(const ulonglong2*)&sW[k * 64 + tx * 4];
                ull a0 = pk2(xv.x), a1 = pk2(xv.y), a2 = pk2(xv.z), a3 = pk2(xv.w);
                ffma2(acc[0], a0, w.x); ffma2(acc[1], a0, w.y);
                ffma2(acc[2], a1, w.x); ffma2(acc[3], a1, w.y);
                ffma2(acc[4], a2, w.x); ffma2(acc[5], a2, w.y);
                ffma2(acc[6], a3, w.x); ffma2(acc[7], a3, w.y);
            }
        }

#pragma unroll
        for (int i = 0; i < 4; ++i) {
            int n = node0 + ty * 4 + i;
            if (n < N) {
                float s = g_dinv[n];
                float o0, o1, o2, o3;
                unpk2(o0, o1, acc[2 * i]);
                unpk2(o2, o3, acc[2 * i + 1]);
                float4 r = {o0 * s, o1 * s, o2 * s, o3 * s};
                *(float4*)&g_Fp[n * 64 + tx * 4] = r;
            }
        }
    }
}

// ---------------- layer-2 aggregation + bias + softmax ----------------------
__global__ void k_agg_softmax(const float* __restrict__ bf, float* __restrict__ out, int N) {
    int tid = threadIdx.x;
    int lane = tid & 15;
    int n = blockIdx.x * 16 + (tid >> 4);
    if (n >= N) return;
    const float4* feat = (const float4*)g_Fp;
    int base = n * 16;
    float4 acc = feat[base + lane];                    // self-loop term
    int beg = g_off[n], end = g_off[n + 1];
    int j = beg;
    for (; j + 8 <= end; j += 8) {
        int u[8];
#pragma unroll
        for (int t = 0; t < 8; ++t) u[t] = g_csr[j + t];
        float4 v[8];
#pragma unroll
        for (int t = 0; t < 8; ++t) v[t] = feat[u[t] * 16 + lane];
#pragma unroll
        for (int t = 0; t < 8; ++t) {
            acc.x += v[t].x; acc.y += v[t].y;
            acc.z += v[t].z; acc.w += v[t].w;
        }
    }
    for (; j < end; ++j) {
        int u = g_csr[j];
        float4 v = feat[u * 16 + lane];
        acc.x += v.x; acc.y += v.y; acc.z += v.z; acc.w += v.w;
    }
    float s = g_dinv[n];
    float4 b4 = ((const float4*)bf)[lane];
    float4 z = {acc.x * s + b4.x, acc.y * s + b4.y,
                acc.z * s + b4.z, acc.w * s + b4.w};

    float m = fmaxf(fmaxf(z.x, z.y), fmaxf(z.z, z.w));
#pragma unroll
    for (int o = 8; o > 0; o >>= 1)
        m = fmaxf(m, __shfl_xor_sync(0xffffffffu, m, o, 16));
    z.x = __expf(z.x - m); z.y = __expf(z.y - m);
    z.z = __expf(z.z - m); z.w = __expf(z.w - m);
    float sum = z.x + z.y + z.z + z.w;
#pragma unroll
    for (int o = 8; o > 0; o >>= 1)
        sum += __shfl_xor_sync(0xffffffffu, sum, o, 16);
    float inv = 1.0f / sum;
    z.x *= inv; z.y *= inv; z.z *= inv; z.w *= inv;
    ((float4*)out)[base + lane] = z;
}

// ---------------- launch ----------------------------------------------------
extern "C" void kernel_launch(void* const* d_in, const int* in_sizes, int n_in,
                              void* d_out, int out_size) {
    const float* X  = (const float*)d_in[0];
    const void*  ei = d_in[1];            // int32 or int64 — detected on device
    const float* Wn = (const float*)d_in[3];
    const float* bn = (const float*)d_in[4];
    const float* Ws = (const float*)d_in[5];
    const float* bs = (const float*)d_in[6];
    const float* Wf = (const float*)d_in[7];
    const float* bf = (const float*)d_in[8];
    float* out = (float*)d_out;

    int N = in_sizes[0] / 64;
    int E = in_sizes[1] / 2;
    int NB = (N + 1023) / 1024;
    int NB64 = (N + 63) / 64;
    size_t smem_bytes = SMEM_FLOATS * sizeof(float);   // ~103 KB

    static int attr_set = 0;
    if (!attr_set) {
        cudaFuncSetAttribute(k_mlp, cudaFuncAttributeMaxDynamicSharedMemorySize,
                             (int)smem_bytes);
        attr_set = 1;
    }

    k_detect<<<1, 1024>>>((const unsigned int*)ei, E);
    k_zero_cnt<<<256, 256>>>(N);
    k_hist<<<(E + 511) / 512, 512>>>(ei, E, N);
    k_scan1<<<NB, 1024>>>(N);
    k_scan2<<<1, 128>>>(NB);
    k_scan3<<<NB, 1024>>>(N, E);
    k_fill<<<(E + 511) / 512, 512>>>(ei, E, N);
    k_agg64<<<(N + 15) / 16, 256>>>(X, N);
    k_mlp<<<NB64, 256, smem_bytes>>>(Wn, bn, Ws, bs, Wf, N);
    k_agg_softmax<<<(N + 15) / 16, 256>>>(bf, out, N);
}

// round 7
// speedup vs baseline: 2.0309x; 1.0015x over previous
#include <cuda_runtime.h>
#include <cuda_bf16.h>

// Problem constants
#define MAXN 100000
#define MAXE 1600000

typedef unsigned long long ull;

// ---------------- scratch (device globals — no runtime allocation) ----------
__device__ int   g_is64;            // 1 if ei_feat is int64, 0 if int32
__device__ int   g_cnt[MAXN];
__device__ float g_dinv[MAXN];
__device__ int   g_off[MAXN + 1];
__device__ int   g_cur[MAXN];
__device__ int   g_csr[MAXE];
__device__ int   g_bsum[256];
__device__ float g_Xt[MAXN * 64];   // aggregated layer-1 input
__device__ float g_Fp[MAXN * 64];   // dinv[n] * (H @ W_fuse)

// ---------------- helpers ---------------------------------------------------
__device__ __forceinline__ int clampN(int v, int N) {
    v = v < 0 ? 0 : v;
    return v >= N ? N - 1 : v;
}

// 32-bit edge read: for int64 input, indices are nonneg < 2^31, so the low
// little-endian word IS the value. Halves ei traffic vs 64-bit loads.
__device__ __forceinline__ int edge_at(const void* ei, int idx) {
    return g_is64 ? ((const int*)ei)[2 * idx] : ((const int*)ei)[idx];
}

// packed f32x2 helpers (Blackwell sm_100+): FFMA2 doubles fp32 FMA throughput
__device__ __forceinline__ ull pk2(float x) {
    ull r;
    asm("mov.b64 %0, {%1, %1};" : "=l"(r) : "f"(x));
    return r;
}
__device__ __forceinline__ void ffma2(ull& d, ull a, ull b) {
    asm("fma.rn.f32x2 %0, %1, %2, %0;" : "+l"(d) : "l"(a), "l"(b));
}
__device__ __forceinline__ void unpk2(float& lo, float& hi, ull v) {
    asm("mov.b64 {%0, %1}, %2;" : "=f"(lo), "=f"(hi) : "l"(v));
}

__device__ __forceinline__ float elu1(float v) {
    return v > 0.f ? v : (__expf(v) - 1.0f);
}

// ---------------- fused dtype detection + counter zeroing -------------------
// Block 0 detects int32 vs int64 from the first <=1024 odd 32-bit words.
// All blocks zero g_cnt (grid-stride).
__global__ void k_detect_zero(const unsigned int* __restrict__ w, int E, int N) {
    if (blockIdx.x == 0) {
        if (threadIdx.x == 0) g_is64 = 1;
        __syncthreads();
        int npairs = E < 1024 ? E : 1024;
        if ((int)threadIdx.x < npairs) {
            if (w[2 * threadIdx.x + 1] != 0u) atomicExch(&g_is64, 0);
        }
    }
    for (int i = blockIdx.x * blockDim.x + threadIdx.x; i < N;
         i += gridDim.x * blockDim.x)
        g_cnt[i] = 0;
}

// ---------------- CSR build -------------------------------------------------
__global__ void k_hist(const void* __restrict__ ei, int E, int N) {
    int e = blockIdx.x * blockDim.x + threadIdx.x;
    if (e < E) {
        int dst = clampN(edge_at(ei, E + e), N);
        atomicAdd(&g_cnt[dst], 1);
    }
}

__global__ void k_scan1(int N) {
    __shared__ int s[1024];
    int tid = threadIdx.x;
    int i = blockIdx.x * 1024 + tid;
    int v = (i < N) ? g_cnt[i] : 0;
    s[tid] = v;
    __syncthreads();
    for (int o = 1; o < 1024; o <<= 1) {
        int t = (tid >= o) ? s[tid - o] : 0;
        __syncthreads();
        s[tid] += t;
        __syncthreads();
    }
    if (i < N) {
        g_off[i] = s[tid] - v;
        g_dinv[i] = rsqrtf((float)(v + 1));
    }
    if (tid == 1023) g_bsum[blockIdx.x] = s[1023];
}

// scan of per-block sums folded in: thread 0 of each block serially sums
// g_bsum[0..bid) (<=98 iterations — trivial), replacing a separate launch.
__global__ void k_scan23(int N, int E) {
    __shared__ int sbase;
    int bid = blockIdx.x;
    if (threadIdx.x == 0) {
        int s = 0;
        for (int b = 0; b < bid; ++b) s += g_bsum[b];
        sbase = s;
    }
    __syncthreads();
    int i = bid * 1024 + threadIdx.x;
    if (i < N) {
        int v = g_off[i] + sbase;
        g_off[i] = v;
        g_cur[i] = v;
    }
    if (i == 0) g_off[N] = E;
}

__global__ void k_fill(const void* __restrict__ ei, int E, int N) {
    int e = blockIdx.x * blockDim.x + threadIdx.x;
    if (e < E) {
        int dst = clampN(edge_at(ei, E + e), N);
        int src = clampN(edge_at(ei, e), N);
        int pos = atomicAdd(&g_cur[dst], 1);
        if (pos < MAXE) g_csr[pos] = src;
    }
}

// ---------------- layer-1 aggregation (prep fused) ---------------------------
// g_Xt[n] = dinv[n] * ( dinv[n]*X[n] + sum_u dinv[u]*X[u] )
// 16 lanes per node, each lane owns one float4 of the 64-wide row.
__global__ void k_agg64(const float* __restrict__ X, int N) {
    int tid = threadIdx.x;
    int lane = tid & 15;
    int n = blockIdx.x * 16 + (tid >> 4);
    if (n >= N) return;
    const float4* feat = (const float4*)X;
    float dn = g_dinv[n];
    float4 self = feat[n * 16 + lane];
    float4 acc = {self.x * dn, self.y * dn, self.z * dn, self.w * dn};
    int beg = g_off[n], end = g_off[n + 1];
    int j = beg;
    for (; j + 8 <= end; j += 8) {
        int u[8];
#pragma unroll
        for (int t = 0; t < 8; ++t) u[t] = g_csr[j + t];
        float du[8]; float4 v[8];
#pragma unroll
        for (int t = 0; t < 8; ++t) { du[t] = g_dinv[u[t]]; v[t] = feat[u[t] * 16 + lane]; }
#pragma unroll
        for (int t = 0; t < 8; ++t) {
            acc.x += du[t] * v[t].x; acc.y += du[t] * v[t].y;
            acc.z += du[t] * v[t].z; acc.w += du[t] * v[t].w;
        }
    }
    for (; j < end; ++j) {
        int u = g_csr[j];
        float du = g_dinv[u];
        float4 v = feat[u * 16 + lane];
        acc.x += du * v.x; acc.y += du * v.y;
        acc.z += du * v.z; acc.w += du * v.w;
    }
    acc.x *= dn; acc.y *= dn; acc.z *= dn; acc.w *= dn;
    ((float4*)g_Xt)[n * 16 + lane] = acc;
}

// ---------------- fused MLP: Fp = dinv * (elu(Xt@Wblk+b) @ Wf) --------------
// Block = 64 nodes, 256 threads, dynamic smem:
//   sHT[256][68]  H transposed (col-major)  17408 floats
//   sW [8192]     Wn+Ws, then reused for Wf k-chunks
//   sB [256]      bias
#define SMEM_HT  17408
#define SMEM_W   (SMEM_HT)            // offset of sW
#define SMEM_B   (SMEM_HT + 8192)     // offset of sB
#define SMEM_FLOATS (SMEM_HT + 8192 + 256)

__global__ __launch_bounds__(256)
void k_mlp(const float* __restrict__ Wn, const float* __restrict__ bn,
           const float* __restrict__ Ws, const float* __restrict__ bs,
           const float* __restrict__ Wf, int N) {
    extern __shared__ float smem[];
    float* sHT = smem;
    float* sW  = smem + SMEM_W;
    float* sB  = smem + SMEM_B;

    int tid = threadIdx.x;
    int node0 = blockIdx.x * 64;

    // load Wn/Ws + bias
    for (int i = tid; i < 4096; i += 256) {
        sW[i]        = Wn[i];
        sW[4096 + i] = Ws[i];
    }
    sB[tid] = (tid < 128) ? bn[tid] : bs[tid - 128];
    __syncthreads();

    // ---------------- Phase A: H = elu(Xt @ blockdiag(Wn,Ws) + b) ----------
    {
        int ww = tid >> 5, lane = tid & 31;
        int hsel = ww >> 2;              // 0: nuc, 1: surf
        int j0 = (ww & 3) * 32;          // local col base within 128
        int c0 = hsel * 128 + j0;        // global col base (32 cols per warp)
        const float* wb = &sW[hsel * 4096 + j0];

        for (int nh = 0; nh < 2; ++nh) {
            int n = node0 + nh * 32 + lane;
            bool valid = n < N;
            float x[32];
            const float4* xp = (const float4*)&g_Xt[(valid ? n : 0) * 64 + hsel * 32];
#pragma unroll
            for (int q = 0; q < 8; ++q) {
                float4 v = valid ? xp[q] : make_float4(0.f, 0.f, 0.f, 0.f);
                x[4 * q + 0] = v.x; x[4 * q + 1] = v.y;
                x[4 * q + 2] = v.z; x[4 * q + 3] = v.w;
            }
            ull acc[16];
#pragma unroll
            for (int i = 0; i < 16; ++i) acc[i] = 0ull;
#pragma unroll
            for (int k = 0; k < 32; ++k) {
                ull a = pk2(x[k]);
                const ulonglong2* wp = (const ulonglong2*)&wb[k * 128];
#pragma unroll
                for (int i = 0; i < 8; ++i) {
                    ulonglong2 w = wp[i];
                    ffma2(acc[2 * i],     a, w.x);
                    ffma2(acc[2 * i + 1], a, w.y);
                }
            }
            int ncol = nh * 32 + lane;
#pragma unroll
            for (int i = 0; i < 8; ++i) {
                float o0, o1, o2, o3;
                unpk2(o0, o1, acc[2 * i]);
                unpk2(o2, o3, acc[2 * i + 1]);
                int c = c0 + 4 * i;
                sHT[(c + 0) * 68 + ncol] = elu1(o0 + sB[c + 0]);
                sHT[(c + 1) * 68 + ncol] = elu1(o1 + sB[c + 1]);
                sHT[(c + 2) * 68 + ncol] = elu1(o2 + sB[c + 2]);
                sHT[(c + 3) * 68 + ncol] = elu1(o3 + sB[c + 3]);
            }
        }
    }

    // ---------------- Phase B: Fp = dinv * (H @ Wf) -------------------------
    {
        int tx = tid & 15;   // col quad: cols tx*4..tx*4+3
        int ty = tid >> 4;   // node quad: nodes ty*4..ty*4+3
        ull acc[8];
#pragma unroll
        for (int i = 0; i < 8; ++i) acc[i] = 0ull;

        for (int kc = 0; kc < 2; ++kc) {
            __syncthreads();   // sW free (phase A done / previous chunk done)
            for (int i = tid; i < 2048; i += 256)
                ((float4*)sW)[i] = ((const float4*)Wf)[kc * 2048 + i];
            __syncthreads();
#pragma unroll 4
            for (int k = 0; k < 128; ++k) {
                int kk = kc * 128 + k;
                float4 xv = *(const float4*)&sHT[kk * 68 + ty * 4];
                ulonglong2 w = *(const ulonglong2*)&sW[k * 64 + tx * 4];
                ull a0 = pk2(xv.x), a1 = pk2(xv.y), a2 = pk2(xv.z), a3 = pk2(xv.w);
                ffma2(acc[0], a0, w.x); ffma2(acc[1], a0, w.y);
                ffma2(acc[2], a1, w.x); ffma2(acc[3], a1, w.y);
                ffma2(acc[4], a2, w.x); ffma2(acc[5], a2, w.y);
                ffma2(acc[6], a3, w.x); ffma2(acc[7], a3, w.y);
            }
        }

#pragma unroll
        for (int i = 0; i < 4; ++i) {
            int n = node0 + ty * 4 + i;
            if (n < N) {
                float s = g_dinv[n];
                float o0, o1, o2, o3;
                unpk2(o0, o1, acc[2 * i]);
                unpk2(o2, o3, acc[2 * i + 1]);
                float4 r = {o0 * s, o1 * s, o2 * s, o3 * s};
                *(float4*)&g_Fp[n * 64 + tx * 4] = r;
            }
        }
    }
}

// ---------------- layer-2 aggregation + bias + softmax ----------------------
__global__ void k_agg_softmax(const float* __restrict__ bf, float* __restrict__ out, int N) {
    int tid = threadIdx.x;
    int lane = tid & 15;
    int n = blockIdx.x * 16 + (tid >> 4);
    if (n >= N) return;
    const float4* feat = (const float4*)g_Fp;
    int base = n * 16;
    float4 acc = feat[base + lane];                    // self-loop term
    int beg = g_off[n], end = g_off[n + 1];
    int j = beg;
    for (; j + 8 <= end; j += 8) {
        int u[8];
#pragma unroll
        for (int t = 0; t < 8; ++t) u[t] = g_csr[j + t];
        float4 v[8];
#pragma unroll
        for (int t = 0; t < 8; ++t) v[t] = feat[u[t] * 16 + lane];
#pragma unroll
        for (int t = 0; t < 8; ++t) {
            acc.x += v[t].x; acc.y += v[t].y;
            acc.z += v[t].z; acc.w += v[t].w;
        }
    }
    for (; j < end; ++j) {
        int u = g_csr[j];
        float4 v = feat[u * 16 + lane];
        acc.x += v.x; acc.y += v.y; acc.z += v.z; acc.w += v.w;
    }
    float s = g_dinv[n];
    float4 b4 = ((const float4*)bf)[lane];
    float4 z = {acc.x * s + b4.x, acc.y * s + b4.y,
                acc.z * s + b4.z, acc.w * s + b4.w};

    float m = fmaxf(fmaxf(z.x, z.y), fmaxf(z.z, z.w));
#pragma unroll
    for (int o = 8; o > 0; o >>= 1)
        m = fmaxf(m, __shfl_xor_sync(0xffffffffu, m, o, 16));
    z.x = __expf(z.x - m); z.y = __expf(z.y - m);
    z.z = __expf(z.z - m); z.w = __expf(z.w - m);
    float sum = z.x + z.y + z.z + z.w;
#pragma unroll
    for (int o = 8; o > 0; o >>= 1)
        sum += __shfl_xor_sync(0xffffffffu, sum, o, 16);
    float inv = 1.0f / sum;
    z.x *= inv; z.y *= inv; z.z *= inv; z.w *= inv;
    ((float4*)out)[base + lane] = z;
}

// ---------------- launch ----------------------------------------------------
extern "C" void kernel_launch(void* const* d_in, const int* in_sizes, int n_in,
                              void* d_out, int out_size) {
    const float* X  = (const float*)d_in[0];
    const void*  ei = d_in[1];            // int32 or int64 — detected on device
    const float* Wn = (const float*)d_in[3];
    const float* bn = (const float*)d_in[4];
    const float* Ws = (const float*)d_in[5];
    const float* bs = (const float*)d_in[6];
    const float* Wf = (const float*)d_in[7];
    const float* bf = (const float*)d_in[8];
    float* out = (float*)d_out;

    int N = in_sizes[0] / 64;
    int E = in_sizes[1] / 2;
    int NB = (N + 1023) / 1024;
    int NB64 = (N + 63) / 64;
    size_t smem_bytes = SMEM_FLOATS * sizeof(float);   // ~103 KB

    cudaFuncSetAttribute(k_mlp, cudaFuncAttributeMaxDynamicSharedMemorySize,
                         (int)smem_bytes);

    k_detect_zero<<<128, 1024>>>((const unsigned int*)ei, E, N);
    k_hist<<<(E + 511) / 512, 512>>>(ei, E, N);
    k_scan1<<<NB, 1024>>>(N);
    k_scan23<<<NB, 1024>>>(N, E);
    k_fill<<<(E + 511) / 512, 512>>>(ei, E, N);
    k_agg64<<<(N + 15) / 16, 256>>>(X, N);
    k_mlp<<<NB64, 256, smem_bytes>>>(Wn, bn, Ws, bs, Wf, N);
    k_agg_softmax<<<(N + 15) / 16, 256>>>(bf, out, N);
}

// round 8
// speedup vs baseline: 2.0891x; 1.0287x over previous
#include <cuda_runtime.h>
#include <cuda_fp16.h>
#include <cuda_bf16.h>

// Problem constants
#define MAXN 100000
#define MAXE 1600000

typedef unsigned long long ull;

// ---------------- scratch (device globals — no runtime allocation) ----------
__device__ int    g_is64;            // 1 if ei_feat is int64, 0 if int32
__device__ int    g_cnt[MAXN];
__device__ float  g_dinv[MAXN];
__device__ int    g_off[MAXN + 1];
__device__ int    g_cur[MAXN];
__device__ int    g_csr[MAXE];
__device__ int    g_bsum[256];
__device__ __half g_Xh[MAXN * 64];   // fp16(dinv[n] * X[n])        (gather src 1)
__device__ float  g_Xt[MAXN * 64];   // aggregated layer-1 input (fp32)
__device__ __half g_Fph[MAXN * 64];  // fp16(dinv[n] * (H @ Wf)[n]) (gather src 2)

// ---------------- helpers ---------------------------------------------------
__device__ __forceinline__ int clampN(int v, int N) {
    v = v < 0 ? 0 : v;
    return v >= N ? N - 1 : v;
}

// 32-bit edge read: indices are nonneg < 2^31, so for int64 input the low
// little-endian word IS the value. Halves ei traffic vs 64-bit loads.
__device__ __forceinline__ int edge_at(const void* ei, int idx) {
    return g_is64 ? ((const int*)ei)[2 * idx] : ((const int*)ei)[idx];
}

// packed f32x2 helpers (Blackwell sm_100+): FFMA2 doubles fp32 FMA throughput
__device__ __forceinline__ ull pk2(float x) {
    ull r;
    asm("mov.b64 %0, {%1, %1};" : "=l"(r) : "f"(x));
    return r;
}
__device__ __forceinline__ void ffma2(ull& d, ull a, ull b) {
    asm("fma.rn.f32x2 %0, %1, %2, %0;" : "+l"(d) : "l"(a), "l"(b));
}
__device__ __forceinline__ void unpk2(float& lo, float& hi, ull v) {
    asm("mov.b64 {%0, %1}, %2;" : "=f"(lo), "=f"(hi) : "l"(v));
}

__device__ __forceinline__ float elu1(float v) {
    return v > 0.f ? v : (__expf(v) - 1.0f);
}

// unpack 4 halves (uint2) and add into a float4 accumulator
__device__ __forceinline__ void hadd4(float4& a, uint2 r) {
    __half2 h0 = *reinterpret_cast<__half2*>(&r.x);
    __half2 h1 = *reinterpret_cast<__half2*>(&r.y);
    float2 f0 = __half22float2(h0);
    float2 f1 = __half22float2(h1);
    a.x += f0.x; a.y += f0.y; a.z += f1.x; a.w += f1.y;
}

__device__ __forceinline__ uint2 pack4h(float a, float b, float c, float d) {
    union { __half2 h[2]; uint2 u; } cv;
    cv.h[0] = __floats2half2_rn(a, b);
    cv.h[1] = __floats2half2_rn(c, d);
    return cv.u;
}

// ---------------- fused dtype detection + counter zeroing -------------------
__global__ void k_detect_zero(const unsigned int* __restrict__ w, int E, int N) {
    if (blockIdx.x == 0) {
        if (threadIdx.x == 0) g_is64 = 1;
        __syncthreads();
        int npairs = E < 1024 ? E : 1024;
        if ((int)threadIdx.x < npairs) {
            if (w[2 * threadIdx.x + 1] != 0u) atomicExch(&g_is64, 0);
        }
    }
    for (int i = blockIdx.x * blockDim.x + threadIdx.x; i < N;
         i += gridDim.x * blockDim.x)
        g_cnt[i] = 0;
}

// ---------------- CSR build -------------------------------------------------
__global__ void k_hist(const void* __restrict__ ei, int E, int N) {
    int e = blockIdx.x * blockDim.x + threadIdx.x;
    if (e < E) {
        int dst = clampN(edge_at(ei, E + e), N);
        atomicAdd(&g_cnt[dst], 1);
    }
}

__global__ void k_scan1(int N) {
    __shared__ int s[1024];
    int tid = threadIdx.x;
    int i = blockIdx.x * 1024 + tid;
    int v = (i < N) ? g_cnt[i] : 0;
    s[tid] = v;
    __syncthreads();
    for (int o = 1; o < 1024; o <<= 1) {
        int t = (tid >= o) ? s[tid - o] : 0;
        __syncthreads();
        s[tid] += t;
        __syncthreads();
    }
    if (i < N) {
        g_off[i] = s[tid] - v;
        g_dinv[i] = rsqrtf((float)(v + 1));
    }
    if (tid == 1023) g_bsum[blockIdx.x] = s[1023];
}

__global__ void k_scan23(int N, int E) {
    __shared__ int sbase;
    int bid = blockIdx.x;
    if (threadIdx.x == 0) {
        int s = 0;
        for (int b = 0; b < bid; ++b) s += g_bsum[b];
        sbase = s;
    }
    __syncthreads();
    int i = bid * 1024 + threadIdx.x;
    if (i < N) {
        int v = g_off[i] + sbase;
        g_off[i] = v;
        g_cur[i] = v;
    }
    if (i == 0) g_off[N] = E;
}

__global__ void k_fill(const void* __restrict__ ei, int E, int N) {
    int e = blockIdx.x * blockDim.x + threadIdx.x;
    if (e < E) {
        int dst = clampN(edge_at(ei, E + e), N);
        int src = clampN(edge_at(ei, e), N);
        int pos = atomicAdd(&g_cur[dst], 1);
        if (pos < MAXE) g_csr[pos] = src;
    }
}

// ---------------- prep: g_Xh = fp16(dinv[n] * X[n]) -------------------------
__global__ void k_prep16(const float* __restrict__ X, int N) {
    int idx = blockIdx.x * blockDim.x + threadIdx.x;   // quad of floats
    int total = N * 16;
    if (idx < total) {
        int n = idx >> 4;
        float s = g_dinv[n];
        float4 v = ((const float4*)X)[idx];
        ((uint2*)g_Xh)[idx] = pack4h(v.x * s, v.y * s, v.z * s, v.w * s);
    }
}

// ---------------- layer-1 aggregation (fp16 gather, fp32 accumulate) --------
// g_Xt[n] = dinv[n] * ( g_Xh[n] + sum_u g_Xh[u] ), all terms pre-scaled by dinv.
// 16 lanes per node; each lane owns 4 halves (8B) of the 128B row.
__global__ void k_agg64(int N) {
    int tid = threadIdx.x;
    int lane = tid & 15;
    int n = blockIdx.x * 16 + (tid >> 4);
    if (n >= N) return;
    const uint2* feat = (const uint2*)g_Xh;
    float4 acc = {0.f, 0.f, 0.f, 0.f};
    hadd4(acc, feat[n * 16 + lane]);                   // self-loop term
    int beg = g_off[n], end = g_off[n + 1];
    int j = beg;
    for (; j + 8 <= end; j += 8) {
        int u[8];
#pragma unroll
        for (int t = 0; t < 8; ++t) u[t] = g_csr[j + t];
        uint2 v[8];
#pragma unroll
        for (int t = 0; t < 8; ++t) v[t] = feat[u[t] * 16 + lane];
#pragma unroll
        for (int t = 0; t < 8; ++t) hadd4(acc, v[t]);
    }
    for (; j < end; ++j)
        hadd4(acc, feat[g_csr[j] * 16 + lane]);
    float dn = g_dinv[n];
    acc.x *= dn; acc.y *= dn; acc.z *= dn; acc.w *= dn;
    ((float4*)g_Xt)[n * 16 + lane] = acc;
}

// ---------------- fused MLP: Fph = fp16(dinv * (elu(Xt@Wblk+b) @ Wf)) -------
#define SMEM_HT  17408
#define SMEM_W   (SMEM_HT)            // offset of sW
#define SMEM_B   (SMEM_HT + 8192)     // offset of sB
#define SMEM_FLOATS (SMEM_HT + 8192 + 256)

__global__ __launch_bounds__(256)
void k_mlp(const float* __restrict__ Wn, const float* __restrict__ bn,
           const float* __restrict__ Ws, const float* __restrict__ bs,
           const float* __restrict__ Wf, int N) {
    extern __shared__ float smem[];
    float* sHT = smem;
    float* sW  = smem + SMEM_W;
    float* sB  = smem + SMEM_B;

    int tid = threadIdx.x;
    int node0 = blockIdx.x * 64;

    for (int i = tid; i < 4096; i += 256) {
        sW[i]        = Wn[i];
        sW[4096 + i] = Ws[i];
    }
    sB[tid] = (tid < 128) ? bn[tid] : bs[tid - 128];
    __syncthreads();

    // ---------------- Phase A: H = elu(Xt @ blockdiag(Wn,Ws) + b) ----------
    {
        int ww = tid >> 5, lane = tid & 31;
        int hsel = ww >> 2;              // 0: nuc, 1: surf
        int j0 = (ww & 3) * 32;          // local col base within 128
        int c0 = hsel * 128 + j0;        // global col base (32 cols per warp)
        const float* wb = &sW[hsel * 4096 + j0];

        for (int nh = 0; nh < 2; ++nh) {
            int n = node0 + nh * 32 + lane;
            bool valid = n < N;
            float x[32];
            const float4* xp = (const float4*)&g_Xt[(valid ? n : 0) * 64 + hsel * 32];
#pragma unroll
            for (int q = 0; q < 8; ++q) {
                float4 v = valid ? xp[q] : make_float4(0.f, 0.f, 0.f, 0.f);
                x[4 * q + 0] = v.x; x[4 * q + 1] = v.y;
                x[4 * q + 2] = v.z; x[4 * q + 3] = v.w;
            }
            ull acc[16];
#pragma unroll
            for (int i = 0; i < 16; ++i) acc[i] = 0ull;
#pragma unroll
            for (int k = 0; k < 32; ++k) {
                ull a = pk2(x[k]);
                const ulonglong2* wp = (const ulonglong2*)&wb[k * 128];
#pragma unroll
                for (int i = 0; i < 8; ++i) {
                    ulonglong2 w = wp[i];
                    ffma2(acc[2 * i],     a, w.x);
                    ffma2(acc[2 * i + 1], a, w.y);
                }
            }
            int ncol = nh * 32 + lane;
#pragma unroll
            for (int i = 0; i < 8; ++i) {
                float o0, o1, o2, o3;
                unpk2(o0, o1, acc[2 * i]);
                unpk2(o2, o3, acc[2 * i + 1]);
                int c = c0 + 4 * i;
                sHT[(c + 0) * 68 + ncol] = elu1(o0 + sB[c + 0]);
                sHT[(c + 1) * 68 + ncol] = elu1(o1 + sB[c + 1]);
                sHT[(c + 2) * 68 + ncol] = elu1(o2 + sB[c + 2]);
                sHT[(c + 3) * 68 + ncol] = elu1(o3 + sB[c + 3]);
            }
        }
    }

    // ---------------- Phase B: Fph = fp16(dinv * (H @ Wf)) ------------------
    {
        int tx = tid & 15;   // col quad: cols tx*4..tx*4+3
        int ty = tid >> 4;   // node quad: nodes ty*4..ty*4+3
        ull acc[8];
#pragma unroll
        for (int i = 0; i < 8; ++i) acc[i] = 0ull;

        for (int kc = 0; kc < 2; ++kc) {
            __syncthreads();
            for (int i = tid; i < 2048; i += 256)
                ((float4*)sW)[i] = ((const float4*)Wf)[kc * 2048 + i];
            __syncthreads();
#pragma unroll 4
            for (int k = 0; k < 128; ++k) {
                int kk = kc * 128 + k;
                float4 xv = *(const float4*)&sHT[kk * 68 + ty * 4];
                ulonglong2 w = *(const ulonglong2*)&sW[k * 64 + tx * 4];
                ull a0 = pk2(xv.x), a1 = pk2(xv.y), a2 = pk2(xv.z), a3 = pk2(xv.w);
                ffma2(acc[0], a0, w.x); ffma2(acc[1], a0, w.y);
                ffma2(acc[2], a1, w.x); ffma2(acc[3], a1, w.y);
                ffma2(acc[4], a2, w.x); ffma2(acc[5], a2, w.y);
                ffma2(acc[6], a3, w.x); ffma2(acc[7], a3, w.y);
            }
        }

#pragma unroll
        for (int i = 0; i < 4; ++i) {
            int n = node0 + ty * 4 + i;
            if (n < N) {
                float s = g_dinv[n];
                float o0, o1, o2, o3;
                unpk2(o0, o1, acc[2 * i]);
                unpk2(o2, o3, acc[2 * i + 1]);
                ((uint2*)g_Fph)[n * 16 + tx] =
                    pack4h(o0 * s, o1 * s, o2 * s, o3 * s);
            }
        }
    }
}

// ---------------- layer-2 aggregation + bias + softmax (fp16 gather) --------
__global__ void k_agg_softmax(const float* __restrict__ bf, float* __restrict__ out, int N) {
    int tid = threadIdx.x;
    int lane = tid & 15;
    int n = blockIdx.x * 16 + (tid >> 4);
    if (n >= N) return;
    const uint2* feat = (const uint2*)g_Fph;
    float4 acc = {0.f, 0.f, 0.f, 0.f};
    hadd4(acc, feat[n * 16 + lane]);                   // self-loop term
    int beg = g_off[n], end = g_off[n + 1];
    int j = beg;
    for (; j + 8 <= end; j += 8) {
        int u[8];
#pragma unroll
        for (int t = 0; t < 8; ++t) u[t] = g_csr[j + t];
        uint2 v[8];
#pragma unroll
        for (int t = 0; t < 8; ++t) v[t] = feat[u[t] * 16 + lane];
#pragma unroll
        for (int t = 0; t < 8; ++t) hadd4(acc, v[t]);
    }
    for (; j < end; ++j)
        hadd4(acc, feat[g_csr[j] * 16 + lane]);
    float s = g_dinv[n];
    float4 b4 = ((const float4*)bf)[lane];
    float4 z = {acc.x * s + b4.x, acc.y * s + b4.y,
                acc.z * s + b4.z, acc.w * s + b4.w};

    // softmax over 64 logits spread across 16 lanes (4 each)
    float m = fmaxf(fmaxf(z.x, z.y), fmaxf(z.z, z.w));
#pragma unroll
    for (int o = 8; o > 0; o >>= 1)
        m = fmaxf(m, __shfl_xor_sync(0xffffffffu, m, o, 16));
    z.x = __expf(z.x - m); z.y = __expf(z.y - m);
    z.z = __expf(z.z - m); z.w = __expf(z.w - m);
    float sum = z.x + z.y + z.z + z.w;
#pragma unroll
    for (int o = 8; o > 0; o >>= 1)
        sum += __shfl_xor_sync(0xffffffffu, sum, o, 16);
    float inv = 1.0f / sum;
    z.x *= inv; z.y *= inv; z.z *= inv; z.w *= inv;
    ((float4*)out)[n * 16 + lane] = z;
}

// ---------------- launch ----------------------------------------------------
extern "C" void kernel_launch(void* const* d_in, const int* in_sizes, int n_in,
                              void* d_out, int out_size) {
    const float* X  = (const float*)d_in[0];
    const void*  ei = d_in[1];            // int32 or int64 — detected on device
    const float* Wn = (const float*)d_in[3];
    const float* bn = (const float*)d_in[4];
    const float* Ws = (const float*)d_in[5];
    const float* bs = (const float*)d_in[6];
    const float* Wf = (const float*)d_in[7];
    const float* bf = (const float*)d_in[8];
    float* out = (float*)d_out;

    int N = in_sizes[0] / 64;
    int E = in_sizes[1] / 2;
    int NB = (N + 1023) / 1024;
    int NB64 = (N + 63) / 64;
    size_t smem_bytes = SMEM_FLOATS * sizeof(float);   // ~103 KB

    cudaFuncSetAttribute(k_mlp, cudaFuncAttributeMaxDynamicSharedMemorySize,
                         (int)smem_bytes);

    k_detect_zero<<<128, 1024>>>((const unsigned int*)ei, E, N);
    k_hist<<<(E + 511) / 512, 512>>>(ei, E, N);
    k_scan1<<<NB, 1024>>>(N);
    k_scan23<<<NB, 1024>>>(N, E);
    k_fill<<<(E + 511) / 512, 512>>>(ei, E, N);
    k_prep16<<<(N * 16 + 255) / 256, 256>>>(X, N);
    k_agg64<<<(N + 15) / 16, 256>>>(N);
    k_mlp<<<NB64, 256, smem_bytes>>>(Wn, bn, Ws, bs, Wf, N);
    k_agg_softmax<<<(N + 15) / 16, 256>>>(bf, out, N);
}

// round 9
// speedup vs baseline: 3.1598x; 1.5125x over previous
#include <cuda_runtime.h>
#include <cuda_fp16.h>
#include <cuda_bf16.h>

// Problem constants
#define MAXN 100000
#define MAXE 1600000

typedef unsigned long long ull;
typedef unsigned int u32;

// ---------------- scratch (device globals — no runtime allocation) ----------
__device__ int    g_is64;            // 1 if ei_feat is int64, 0 if int32
__device__ int    g_cnt[MAXN];
__device__ float  g_dinv[MAXN];
__device__ int    g_off[MAXN + 1];
__device__ int    g_cur[MAXN];
__device__ int    g_csr[MAXE];
__device__ int    g_bsum[256];
__device__ __half g_Xh[MAXN * 64];   // fp16(dinv[n] * X[n])        (gather src 1)
__device__ float  g_Xt[MAXN * 64];   // aggregated layer-1 input (fp32)
__device__ __half g_Fph[MAXN * 64];  // fp16(dinv[n] * (H @ Wf)[n]) (gather src 2)
// pre-transposed fp16 weights, padded rows for conflict-free ldmatrix
__device__ __half g_WTa[256 * 40];   // [n(256)][k(32)+8pad]  (Wn rows 0-127, Ws 128-255)
__device__ __half g_WfT[64 * 264];   // [n(64)][k(256)+8pad]

// ---------------- helpers ---------------------------------------------------
__device__ __forceinline__ int clampN(int v, int N) {
    v = v < 0 ? 0 : v;
    return v >= N ? N - 1 : v;
}

__device__ __forceinline__ int edge_at(const void* ei, int idx) {
    return g_is64 ? ((const int*)ei)[2 * idx] : ((const int*)ei)[idx];
}

__device__ __forceinline__ float elu1(float v) {
    return v > 0.f ? v : (__expf(v) - 1.0f);
}

__device__ __forceinline__ void hadd4(float4& a, uint2 r) {
    __half2 h0 = *reinterpret_cast<__half2*>(&r.x);
    __half2 h1 = *reinterpret_cast<__half2*>(&r.y);
    float2 f0 = __half22float2(h0);
    float2 f1 = __half22float2(h1);
    a.x += f0.x; a.y += f0.y; a.z += f1.x; a.w += f1.y;
}

__device__ __forceinline__ uint2 pack4h(float a, float b, float c, float d) {
    union { __half2 h[2]; uint2 u; } cv;
    cv.h[0] = __floats2half2_rn(a, b);
    cv.h[1] = __floats2half2_rn(c, d);
    return cv.u;
}

__device__ __forceinline__ u32 s2u(const void* p) {
    return (u32)__cvta_generic_to_shared(p);
}
__device__ __forceinline__ void ldsm4(u32* r, u32 a) {
    asm volatile("ldmatrix.sync.aligned.m8n8.x4.shared.b16 {%0,%1,%2,%3}, [%4];"
        : "=r"(r[0]), "=r"(r[1]), "=r"(r[2]), "=r"(r[3]) : "r"(a));
}
__device__ __forceinline__ void ldsm2(u32* r, u32 a) {
    asm volatile("ldmatrix.sync.aligned.m8n8.x2.shared.b16 {%0,%1}, [%2];"
        : "=r"(r[0]), "=r"(r[1]) : "r"(a));
}
__device__ __forceinline__ void mma16816(float* c, const u32* a, const u32* b) {
    asm volatile("mma.sync.aligned.m16n8k16.row.col.f32.f16.f16.f32 "
        "{%0,%1,%2,%3}, {%4,%5,%6,%7}, {%8,%9}, {%0,%1,%2,%3};"
        : "+f"(c[0]), "+f"(c[1]), "+f"(c[2]), "+f"(c[3])
        : "r"(a[0]), "r"(a[1]), "r"(a[2]), "r"(a[3]), "r"(b[0]), "r"(b[1]));
}

// ---------------- fused dtype detection + counter zeroing -------------------
__global__ void k_detect_zero(const unsigned int* __restrict__ w, int E, int N) {
    if (blockIdx.x == 0) {
        if (threadIdx.x == 0) g_is64 = 1;
        __syncthreads();
        int npairs = E < 1024 ? E : 1024;
        if ((int)threadIdx.x < npairs) {
            if (w[2 * threadIdx.x + 1] != 0u) atomicExch(&g_is64, 0);
        }
    }
    for (int i = blockIdx.x * blockDim.x + threadIdx.x; i < N;
         i += gridDim.x * blockDim.x)
        g_cnt[i] = 0;
}

// ---------------- weight pre-transpose to fp16 (one block) ------------------
__global__ void k_prepw(const float* __restrict__ Wn, const float* __restrict__ Ws,
                        const float* __restrict__ Wf) {
    int tid = threadIdx.x;
    for (int idx = tid; idx < 4096; idx += 256) {
        int k = idx >> 7, n = idx & 127;           // Wn/Ws are [32][128]
        g_WTa[n * 40 + k]         = __float2half_rn(Wn[idx]);
        g_WTa[(n + 128) * 40 + k] = __float2half_rn(Ws[idx]);
    }
    for (int idx = tid; idx < 16384; idx += 256) {
        int k = idx >> 6, n = idx & 63;            // Wf is [256][64]
        g_WfT[n * 264 + k] = __float2half_rn(Wf[idx]);
    }
}

// ---------------- CSR build -------------------------------------------------
__global__ void k_hist(const void* __restrict__ ei, int E, int N) {
    int e = blockIdx.x * blockDim.x + threadIdx.x;
    if (e < E) {
        int dst = clampN(edge_at(ei, E + e), N);
        atomicAdd(&g_cnt[dst], 1);
    }
}

__global__ void k_scan1(int N) {
    __shared__ int s[1024];
    int tid = threadIdx.x;
    int i = blockIdx.x * 1024 + tid;
    int v = (i < N) ? g_cnt[i] : 0;
    s[tid] = v;
    __syncthreads();
    for (int o = 1; o < 1024; o <<= 1) {
        int t = (tid >= o) ? s[tid - o] : 0;
        __syncthreads();
        s[tid] += t;
        __syncthreads();
    }
    if (i < N) {
        g_off[i] = s[tid] - v;
        g_dinv[i] = rsqrtf((float)(v + 1));
    }
    if (tid == 1023) g_bsum[blockIdx.x] = s[1023];
}

__global__ void k_scan23(int N, int E) {
    __shared__ int sbase;
    int bid = blockIdx.x;
    if (threadIdx.x == 0) {
        int s = 0;
        for (int b = 0; b < bid; ++b) s += g_bsum[b];
        sbase = s;
    }
    __syncthreads();
    int i = bid * 1024 + threadIdx.x;
    if (i < N) {
        int v = g_off[i] + sbase;
        g_off[i] = v;
        g_cur[i] = v;
    }
    if (i == 0) g_off[N] = E;
}

__global__ void k_fill(const void* __restrict__ ei, int E, int N) {
    int e = blockIdx.x * blockDim.x + threadIdx.x;
    if (e < E) {
        int dst = clampN(edge_at(ei, E + e), N);
        int src = clampN(edge_at(ei, e), N);
        int pos = atomicAdd(&g_cur[dst], 1);
        if (pos < MAXE) g_csr[pos] = src;
    }
}

// ---------------- prep: g_Xh = fp16(dinv[n] * X[n]) -------------------------
__global__ void k_prep16(const float* __restrict__ X, int N) {
    int idx = blockIdx.x * blockDim.x + threadIdx.x;   // quad of floats
    int total = N * 16;
    if (idx < total) {
        int n = idx >> 4;
        float s = g_dinv[n];
        float4 v = ((const float4*)X)[idx];
        ((uint2*)g_Xh)[idx] = pack4h(v.x * s, v.y * s, v.z * s, v.w * s);
    }
}

// ---------------- layer-1 aggregation (fp16 gather, fp32 accumulate) --------
__global__ void k_agg64(int N) {
    int tid = threadIdx.x;
    int lane = tid & 15;
    int n = blockIdx.x * 16 + (tid >> 4);
    if (n >= N) return;
    const uint2* feat = (const uint2*)g_Xh;
    float4 acc = {0.f, 0.f, 0.f, 0.f};
    hadd4(acc, feat[n * 16 + lane]);                   // self-loop term
    int beg = g_off[n], end = g_off[n + 1];
    int j = beg;
    for (; j + 8 <= end; j += 8) {
        int u[8];
#pragma unroll
        for (int t = 0; t < 8; ++t) u[t] = g_csr[j + t];
        uint2 v[8];
#pragma unroll
        for (int t = 0; t < 8; ++t) v[t] = feat[u[t] * 16 + lane];
#pragma unroll
        for (int t = 0; t < 8; ++t) hadd4(acc, v[t]);
    }
    for (; j < end; ++j)
        hadd4(acc, feat[g_csr[j] * 16 + lane]);
    float dn = g_dinv[n];
    acc.x *= dn; acc.y *= dn; acc.z *= dn; acc.w *= dn;
    ((float4*)g_Xt)[n * 16 + lane] = acc;
}

// ---------------- HMMA MLP: Fph = fp16(dinv * (elu(Xt@Wblk+b) @ Wf)) --------
// Block = 64 nodes, 256 threads (8 warps), ~96.3 KB dynamic smem.
// Layouts (halves): sXh [64][72], sWTa [256][40], sH [64][264], sWfT [64][264]
// (row strides 144/80/528/528 B — 16B-aligned, bank-shifted: conflict-free ldmatrix)
#define OFF_XH   0
#define OFF_WTA  4608
#define OFF_H    14848
#define OFF_WFT  31744
#define HALVES_TOTAL 48640
#define MLP_SMEM_BYTES (HALVES_TOTAL * 2 + 256 * 4 + 64 * 4)

__global__ __launch_bounds__(256)
void k_mlp(const float* __restrict__ bn, const float* __restrict__ bs, int N) {
    extern __shared__ __half smh[];
    float* sBias = (float*)(smh + HALVES_TOTAL);
    float* sDinv = sBias + 256;

    int tid = threadIdx.x;
    int node0 = blockIdx.x * 64;
    int w = tid >> 5, lane = tid & 31;

    // ---- stage: weights (direct fp16 copies), Xt->fp16, bias, dinv ----
    {
        const uint4* s1 = (const uint4*)g_WTa;
        uint4* d1 = (uint4*)(smh + OFF_WTA);
        for (int i = tid; i < 1280; i += 256) d1[i] = s1[i];
        const uint4* s2 = (const uint4*)g_WfT;
        uint4* d2 = (uint4*)(smh + OFF_WFT);
        for (int i = tid; i < 2112; i += 256) d2[i] = s2[i];
        for (int idx = tid; idx < 2048; idx += 256) {   // float2 units of Xt
            int row = idx >> 5, cp = idx & 31;
            int n = node0 + row;
            float2 f = (n < N) ? ((const float2*)g_Xt)[n * 32 + cp]
                               : make_float2(0.f, 0.f);
            *(__half2*)&smh[OFF_XH + row * 72 + cp * 2] = __floats2half2_rn(f.x, f.y);
        }
        sBias[tid] = (tid < 128) ? bn[tid] : bs[tid - 128];
        if (tid < 64) {
            int n = node0 + tid;
            sDinv[tid] = (n < N) ? g_dinv[n] : 0.f;
        }
    }
    __syncthreads();

    // ---- Phase A: H[64][256] = elu(Xt @ blockdiag(Wn,Ws) + b), warp = 32 cols
    {
        int hsel = w >> 2;              // warps 0-3: cols 0-127 (nuc), 4-7: surf
        int n0w = w * 32;               // global col base
        float c[4][4][4];
#pragma unroll
        for (int mt = 0; mt < 4; ++mt)
#pragma unroll
            for (int nt = 0; nt < 4; ++nt)
#pragma unroll
                for (int i = 0; i < 4; ++i) c[mt][nt][i] = 0.f;

        u32 bfr[4][2][2];
#pragma unroll
        for (int nt = 0; nt < 4; ++nt)
#pragma unroll
            for (int ks = 0; ks < 2; ++ks) {
                int row = n0w + nt * 8 + (lane & 7);
                int col = ks * 16 + ((lane >> 3) & 1) * 8;
                ldsm2(bfr[nt][ks], s2u(&smh[OFF_WTA + row * 40 + col]));
            }

#pragma unroll
        for (int mt = 0; mt < 4; ++mt) {
            u32 afr[2][4];
#pragma unroll
            for (int ks = 0; ks < 2; ++ks) {
                int row = mt * 16 + (lane & 15);
                int col = hsel * 32 + ks * 16 + (lane >> 4) * 8;
                ldsm4(afr[ks], s2u(&smh[OFF_XH + row * 72 + col]));
            }
#pragma unroll
            for (int nt = 0; nt < 4; ++nt) {
                mma16816(c[mt][nt], afr[0], bfr[nt][0]);
                mma16816(c[mt][nt], afr[1], bfr[nt][1]);
            }
        }

        // epilogue: bias + elu -> sH fp16
#pragma unroll
        for (int mt = 0; mt < 4; ++mt)
#pragma unroll
            for (int nt = 0; nt < 4; ++nt) {
                int colg = n0w + nt * 8 + 2 * (lane & 3);
                float b0 = sBias[colg], b1 = sBias[colg + 1];
                int r0 = mt * 16 + (lane >> 2);
                *(__half2*)&smh[OFF_H + r0 * 264 + colg] =
                    __floats2half2_rn(elu1(c[mt][nt][0] + b0), elu1(c[mt][nt][1] + b1));
                *(__half2*)&smh[OFF_H + (r0 + 8) * 264 + colg] =
                    __floats2half2_rn(elu1(c[mt][nt][2] + b0), elu1(c[mt][nt][3] + b1));
            }
    }
    __syncthreads();

    // ---- Phase B: Fp[64][64] = dinv * (H @ Wf), warp tile 16x32, K=256 ----
    {
        int m0 = (w & 3) * 16, n0b = (w >> 2) * 32;
        float c2[4][4];
#pragma unroll
        for (int nt = 0; nt < 4; ++nt)
#pragma unroll
            for (int i = 0; i < 4; ++i) c2[nt][i] = 0.f;

        for (int ks = 0; ks < 16; ++ks) {
            int k0 = ks * 16;
            u32 afr[4];
            {
                int row = m0 + (lane & 15);
                int col = k0 + (lane >> 4) * 8;
                ldsm4(afr, s2u(&smh[OFF_H + row * 264 + col]));
            }
#pragma unroll
            for (int nt = 0; nt < 4; ++nt) {
                u32 bfr[2];
                int row = n0b + nt * 8 + (lane & 7);
                int col = k0 + ((lane >> 3) & 1) * 8;
                ldsm2(bfr, s2u(&smh[OFF_WFT + row * 264 + col]));
                mma16816(c2[nt], afr, bfr);
            }
        }

#pragma unroll
        for (int nt = 0; nt < 4; ++nt) {
            int colg = n0b + nt * 8 + 2 * (lane & 3);
            int r0 = m0 + (lane >> 2), r1 = r0 + 8;
            int ng0 = node0 + r0, ng1 = node0 + r1;
            if (ng0 < N) {
                float d = sDinv[r0];
                *(__half2*)&g_Fph[ng0 * 64 + colg] =
                    __floats2half2_rn(c2[nt][0] * d, c2[nt][1] * d);
            }
            if (ng1 < N) {
                float d = sDinv[r1];
                *(__half2*)&g_Fph[ng1 * 64 + colg] =
                    __floats2half2_rn(c2[nt][2] * d, c2[nt][3] * d);
            }
        }
    }
}

// ---------------- layer-2 aggregation + bias + softmax (fp16 gather) --------
__global__ void k_agg_softmax(const float* __restrict__ bf, float* __restrict__ out, int N) {
    int tid = threadIdx.x;
    int lane = tid & 15;
    int n = blockIdx.x * 16 + (tid >> 4);
    if (n >= N) return;
    const uint2* feat = (const uint2*)g_Fph;
    float4 acc = {0.f, 0.f, 0.f, 0.f};
    hadd4(acc, feat[n * 16 + lane]);                   // self-loop term
    int beg = g_off[n], end = g_off[n + 1];
    int j = beg;
    for (; j + 8 <= end; j += 8) {
        int u[8];
#pragma unroll
        for (int t = 0; t < 8; ++t) u[t] = g_csr[j + t];
        uint2 v[8];
#pragma unroll
        for (int t = 0; t < 8; ++t) v[t] = feat[u[t] * 16 + lane];
#pragma unroll
        for (int t = 0; t < 8; ++t) hadd4(acc, v[t]);
    }
    for (; j < end; ++j)
        hadd4(acc, feat[g_csr[j] * 16 + lane]);
    float s = g_dinv[n];
    float4 b4 = ((const float4*)bf)[lane];
    float4 z = {acc.x * s + b4.x, acc.y * s + b4.y,
                acc.z * s + b4.z, acc.w * s + b4.w};

    float m = fmaxf(fmaxf(z.x, z.y), fmaxf(z.z, z.w));
#pragma unroll
    for (int o = 8; o > 0; o >>= 1)
        m = fmaxf(m, __shfl_xor_sync(0xffffffffu, m, o, 16));
    z.x = __expf(z.x - m); z.y = __expf(z.y - m);
    z.z = __expf(z.z - m); z.w = __expf(z.w - m);
    float sum = z.x + z.y + z.z + z.w;
#pragma unroll
    for (int o = 8; o > 0; o >>= 1)
        sum += __shfl_xor_sync(0xffffffffu, sum, o, 16);
    float inv = 1.0f / sum;
    z.x *= inv; z.y *= inv; z.z *= inv; z.w *= inv;
    ((float4*)out)[n * 16 + lane] = z;
}

// ---------------- launch ----------------------------------------------------
extern "C" void kernel_launch(void* const* d_in, const int* in_sizes, int n_in,
                              void* d_out, int out_size) {
    const float* X  = (const float*)d_in[0];
    const void*  ei = d_in[1];            // int32 or int64 — detected on device
    const float* Wn = (const float*)d_in[3];
    const float* bn = (const float*)d_in[4];
    const float* Ws = (const float*)d_in[5];
    const float* bs = (const float*)d_in[6];
    const float* Wf = (const float*)d_in[7];
    const float* bf = (const float*)d_in[8];
    float* out = (float*)d_out;

    int N = in_sizes[0] / 64;
    int E = in_sizes[1] / 2;
    int NB = (N + 1023) / 1024;
    int NB64 = (N + 63) / 64;

    cudaFuncSetAttribute(k_mlp, cudaFuncAttributeMaxDynamicSharedMemorySize,
                         MLP_SMEM_BYTES);

    k_detect_zero<<<128, 1024>>>((const unsigned int*)ei, E, N);
    k_prepw<<<1, 256>>>(Wn, Ws, Wf);
    k_hist<<<(E + 511) / 512, 512>>>(ei, E, N);
    k_scan1<<<NB, 1024>>>(N);
    k_scan23<<<NB, 1024>>>(N, E);
    k_fill<<<(E + 511) / 512, 512>>>(ei, E, N);
    k_prep16<<<(N * 16 + 255) / 256, 256>>>(X, N);
    k_agg64<<<(N + 15) / 16, 256>>>(N);
    k_mlp<<<NB64, 256, MLP_SMEM_BYTES>>>(bn, bs, N);
    k_agg_softmax<<<(N + 15) / 16, 256>>>(bf, out, N);
}

// round 10
// speedup vs baseline: 3.3514x; 1.0606x over previous
#include <cuda_runtime.h>
#include <cuda_fp16.h>
#include <cuda_bf16.h>

// Problem constants
#define MAXN 100000
#define MAXE 1600000

typedef unsigned long long ull;
typedef unsigned int u32;

// ---------------- scratch (device globals — no runtime allocation) ----------
__device__ int    g_is64;            // 1 if ei_feat is int64, 0 if int32
__device__ int    g_cnt[MAXN];
__device__ float  g_dinv[MAXN];
__device__ int    g_off[MAXN + 1];
__device__ int    g_cur[MAXN];
__device__ int    g_csr[MAXE];
__device__ int    g_bsum[256];
__device__ __half g_Xh[MAXN * 64];   // fp16(dinv[n] * X[n])        (gather src 1)
__device__ __half g_Fph[MAXN * 64];  // fp16(dinv[n] * (H @ Wf)[n]) (gather src 2)
// pre-transposed fp16 weights, padded rows for conflict-free ldmatrix
__device__ __half g_WTa[256 * 40];   // [n(256)][k(32)+8pad]  (Wn rows 0-127, Ws 128-255)
__device__ __half g_WfT[64 * 264];   // [n(64)][k(256)+8pad]

// ---------------- helpers ---------------------------------------------------
__device__ __forceinline__ int clampN(int v, int N) {
    v = v < 0 ? 0 : v;
    return v >= N ? N - 1 : v;
}

__device__ __forceinline__ int edge_at(const void* ei, int idx) {
    return g_is64 ? ((const int*)ei)[2 * idx] : ((const int*)ei)[idx];
}

__device__ __forceinline__ float elu1(float v) {
    return v > 0.f ? v : (__expf(v) - 1.0f);
}

__device__ __forceinline__ void hadd4(float4& a, uint2 r) {
    __half2 h0 = *reinterpret_cast<__half2*>(&r.x);
    __half2 h1 = *reinterpret_cast<__half2*>(&r.y);
    float2 f0 = __half22float2(h0);
    float2 f1 = __half22float2(h1);
    a.x += f0.x; a.y += f0.y; a.z += f1.x; a.w += f1.y;
}

__device__ __forceinline__ uint2 pack4h(float a, float b, float c, float d) {
    union { __half2 h[2]; uint2 u; } cv;
    cv.h[0] = __floats2half2_rn(a, b);
    cv.h[1] = __floats2half2_rn(c, d);
    return cv.u;
}

__device__ __forceinline__ u32 s2u(const void* p) {
    return (u32)__cvta_generic_to_shared(p);
}
__device__ __forceinline__ void ldsm4(u32* r, u32 a) {
    asm volatile("ldmatrix.sync.aligned.m8n8.x4.shared.b16 {%0,%1,%2,%3}, [%4];"
        : "=r"(r[0]), "=r"(r[1]), "=r"(r[2]), "=r"(r[3]) : "r"(a));
}
__device__ __forceinline__ void ldsm2(u32* r, u32 a) {
    asm volatile("ldmatrix.sync.aligned.m8n8.x2.shared.b16 {%0,%1}, [%2];"
        : "=r"(r[0]), "=r"(r[1]) : "r"(a));
}
__device__ __forceinline__ void mma16816(float* c, const u32* a, const u32* b) {
    asm volatile("mma.sync.aligned.m16n8k16.row.col.f32.f16.f16.f32 "
        "{%0,%1,%2,%3}, {%4,%5,%6,%7}, {%8,%9}, {%0,%1,%2,%3};"
        : "+f"(c[0]), "+f"(c[1]), "+f"(c[2]), "+f"(c[3])
        : "r"(a[0]), "r"(a[1]), "r"(a[2]), "r"(a[3]), "r"(b[0]), "r"(b[1]));
}

// ---------------- fused dtype detection + counter zeroing -------------------
__global__ void k_detect_zero(const unsigned int* __restrict__ w, int E, int N) {
    if (blockIdx.x == 0) {
        if (threadIdx.x == 0) g_is64 = 1;
        __syncthreads();
        int npairs = E < 1024 ? E : 1024;
        if ((int)threadIdx.x < npairs) {
            if (w[2 * threadIdx.x + 1] != 0u) atomicExch(&g_is64, 0);
        }
    }
    for (int i = blockIdx.x * blockDim.x + threadIdx.x; i < N;
         i += gridDim.x * blockDim.x)
        g_cnt[i] = 0;
}

// ---------------- weight pre-transpose to fp16 (grid-stride, 16 blocks) -----
__global__ void k_prepw(const float* __restrict__ Wn, const float* __restrict__ Ws,
                        const float* __restrict__ Wf) {
    int stride = gridDim.x * blockDim.x;
    int tid = blockIdx.x * blockDim.x + threadIdx.x;
    for (int idx = tid; idx < 4096; idx += stride) {
        int k = idx >> 7, n = idx & 127;           // Wn/Ws are [32][128]
        g_WTa[n * 40 + k]         = __float2half_rn(Wn[idx]);
        g_WTa[(n + 128) * 40 + k] = __float2half_rn(Ws[idx]);
    }
    for (int idx = tid; idx < 16384; idx += stride) {
        int k = idx >> 6, n = idx & 63;            // Wf is [256][64]
        g_WfT[n * 264 + k] = __float2half_rn(Wf[idx]);
    }
}

// ---------------- CSR build -------------------------------------------------
__global__ void k_hist(const void* __restrict__ ei, int E, int N) {
    int e = blockIdx.x * blockDim.x + threadIdx.x;
    if (e < E) {
        int dst = clampN(edge_at(ei, E + e), N);
        atomicAdd(&g_cnt[dst], 1);
    }
}

__global__ void k_scan1(int N) {
    __shared__ int s[1024];
    int tid = threadIdx.x;
    int i = blockIdx.x * 1024 + tid;
    int v = (i < N) ? g_cnt[i] : 0;
    s[tid] = v;
    __syncthreads();
    for (int o = 1; o < 1024; o <<= 1) {
        int t = (tid >= o) ? s[tid - o] : 0;
        __syncthreads();
        s[tid] += t;
        __syncthreads();
    }
    if (i < N) {
        g_off[i] = s[tid] - v;
        g_dinv[i] = rsqrtf((float)(v + 1));
    }
    if (tid == 1023) g_bsum[blockIdx.x] = s[1023];
}

__global__ void k_scan23(int N, int E) {
    __shared__ int sbase;
    int bid = blockIdx.x;
    if (threadIdx.x == 0) {
        int s = 0;
        for (int b = 0; b < bid; ++b) s += g_bsum[b];
        sbase = s;
    }
    __syncthreads();
    int i = bid * 1024 + threadIdx.x;
    if (i < N) {
        int v = g_off[i] + sbase;
        g_off[i] = v;
        g_cur[i] = v;
    }
    if (i == 0) g_off[N] = E;
}

__global__ void k_fill(const void* __restrict__ ei, int E, int N) {
    int e = blockIdx.x * blockDim.x + threadIdx.x;
    if (e < E) {
        int dst = clampN(edge_at(ei, E + e), N);
        int src = clampN(edge_at(ei, e), N);
        int pos = atomicAdd(&g_cur[dst], 1);
        if (pos < MAXE) g_csr[pos] = src;
    }
}

// ---------------- prep: g_Xh = fp16(dinv[n] * X[n]) -------------------------
__global__ void k_prep16(const float* __restrict__ X, int N) {
    int idx = blockIdx.x * blockDim.x + threadIdx.x;   // quad of floats
    int total = N * 16;
    if (idx < total) {
        int n = idx >> 4;
        float s = g_dinv[n];
        float4 v = ((const float4*)X)[idx];
        ((uint2*)g_Xh)[idx] = pack4h(v.x * s, v.y * s, v.z * s, v.w * s);
    }
}

// ---------------- fused agg + HMMA MLP --------------------------------------
// Per block (64 nodes, 256 threads, ~96.3 KB dynamic smem):
//   Phase 0 (gather): Xt[n] = dinv[n]*(Xh[n] + sum_u Xh[u]) in fp32 regs,
//                     packed straight into sXh fp16 (no g_Xt round trip).
//   Phase A (HMMA):   H = elu(Xt @ blockdiag(Wn,Ws) + b) -> sH fp16
//   Phase B (HMMA):   Fph = fp16(dinv * (H @ Wf)) -> global
// Layouts (halves): sXh [64][72], sWTa [256][40], sH [64][264], sWfT [64][264]
#define OFF_XH   0
#define OFF_WTA  4608
#define OFF_H    14848
#define OFF_WFT  31744
#define HALVES_TOTAL 48640
#define MLP_SMEM_BYTES (HALVES_TOTAL * 2 + 256 * 4 + 64 * 4)

__global__ __launch_bounds__(256)
void k_aggmlp(const float* __restrict__ bn, const float* __restrict__ bs, int N) {
    extern __shared__ __half smh[];
    float* sBias = (float*)(smh + HALVES_TOTAL);
    float* sDinv = sBias + 256;

    int tid = threadIdx.x;
    int node0 = blockIdx.x * 64;
    int w = tid >> 5, lane = tid & 31;

    // ---- stage weights + bias + dinv ----
    {
        const uint4* s1 = (const uint4*)g_WTa;
        uint4* d1 = (uint4*)(smh + OFF_WTA);
        for (int i = tid; i < 1280; i += 256) d1[i] = s1[i];
        const uint4* s2 = (const uint4*)g_WfT;
        uint4* d2 = (uint4*)(smh + OFF_WFT);
        for (int i = tid; i < 2112; i += 256) d2[i] = s2[i];
        sBias[tid] = (tid < 128) ? bn[tid] : bs[tid - 128];
        if (tid < 64) {
            int n = node0 + tid;
            sDinv[tid] = (n < N) ? g_dinv[n] : 0.f;
        }
    }

    // ---- Phase 0: gather-aggregate straight into sXh (fp16) ----
    {
        int glane = tid & 15;            // 16 lanes per node, 4 halves each
        int nsub = tid >> 4;             // 16 nodes per pass, 4 passes
        const uint2* feat = (const uint2*)g_Xh;
#pragma unroll
        for (int pass = 0; pass < 4; ++pass) {
            int row = pass * 16 + nsub;
            int n = node0 + row;
            float4 acc = {0.f, 0.f, 0.f, 0.f};
            if (n < N) {
                hadd4(acc, feat[n * 16 + glane]);      // self-loop term
                int beg = g_off[n], end = g_off[n + 1];
                int j = beg;
                for (; j + 8 <= end; j += 8) {
                    int u[8];
#pragma unroll
                    for (int t = 0; t < 8; ++t) u[t] = g_csr[j + t];
                    uint2 v[8];
#pragma unroll
                    for (int t = 0; t < 8; ++t) v[t] = feat[u[t] * 16 + glane];
#pragma unroll
                    for (int t = 0; t < 8; ++t) hadd4(acc, v[t]);
                }
                for (; j < end; ++j)
                    hadd4(acc, feat[g_csr[j] * 16 + glane]);
                float dn = g_dinv[n];
                acc.x *= dn; acc.y *= dn; acc.z *= dn; acc.w *= dn;
            }
            *(uint2*)&smh[OFF_XH + row * 72 + glane * 4] =
                pack4h(acc.x, acc.y, acc.z, acc.w);
        }
    }
    __syncthreads();

    // ---- Phase A: H[64][256] = elu(Xt @ blockdiag(Wn,Ws) + b), warp = 32 cols
    {
        int hsel = w >> 2;              // warps 0-3: cols 0-127 (nuc), 4-7: surf
        int n0w = w * 32;               // global col base
        float c[4][4][4];
#pragma unroll
        for (int mt = 0; mt < 4; ++mt)
#pragma unroll
            for (int nt = 0; nt < 4; ++nt)
#pragma unroll
                for (int i = 0; i < 4; ++i) c[mt][nt][i] = 0.f;

        u32 bfr[4][2][2];
#pragma unroll
        for (int nt = 0; nt < 4; ++nt)
#pragma unroll
            for (int ks = 0; ks < 2; ++ks) {
                int row = n0w + nt * 8 + (lane & 7);
                int col = ks * 16 + ((lane >> 3) & 1) * 8;
                ldsm2(bfr[nt][ks], s2u(&smh[OFF_WTA + row * 40 + col]));
            }

#pragma unroll
        for (int mt = 0; mt < 4; ++mt) {
            u32 afr[2][4];
#pragma unroll
            for (int ks = 0; ks < 2; ++ks) {
                int row = mt * 16 + (lane & 15);
                int col = hsel * 32 + ks * 16 + (lane >> 4) * 8;
                ldsm4(afr[ks], s2u(&smh[OFF_XH + row * 72 + col]));
            }
#pragma unroll
            for (int nt = 0; nt < 4; ++nt) {
                mma16816(c[mt][nt], afr[0], bfr[nt][0]);
                mma16816(c[mt][nt], afr[1], bfr[nt][1]);
            }
        }

        // epilogue: bias + elu -> sH fp16
#pragma unroll
        for (int mt = 0; mt < 4; ++mt)
#pragma unroll
            for (int nt = 0; nt < 4; ++nt) {
                int colg = n0w + nt * 8 + 2 * (lane & 3);
                float b0 = sBias[colg], b1 = sBias[colg + 1];
                int r0 = mt * 16 + (lane >> 2);
                *(__half2*)&smh[OFF_H + r0 * 264 + colg] =
                    __floats2half2_rn(elu1(c[mt][nt][0] + b0), elu1(c[mt][nt][1] + b1));
                *(__half2*)&smh[OFF_H + (r0 + 8) * 264 + colg] =
                    __floats2half2_rn(elu1(c[mt][nt][2] + b0), elu1(c[mt][nt][3] + b1));
            }
    }
    __syncthreads();

    // ---- Phase B: Fp[64][64] = dinv * (H @ Wf), warp tile 16x32, K=256 ----
    {
        int m0 = (w & 3) * 16, n0b = (w >> 2) * 32;
        float c2[4][4];
#pragma unroll
        for (int nt = 0; nt < 4; ++nt)
#pragma unroll
            for (int i = 0; i < 4; ++i) c2[nt][i] = 0.f;

        for (int ks = 0; ks < 16; ++ks) {
            int k0 = ks * 16;
            u32 afr[4];
            {
                int row = m0 + (lane & 15);
                int col = k0 + (lane >> 4) * 8;
                ldsm4(afr, s2u(&smh[OFF_H + row * 264 + col]));
            }
#pragma unroll
            for (int nt = 0; nt < 4; ++nt) {
                u32 bfr[2];
                int row = n0b + nt * 8 + (lane & 7);
                int col = k0 + ((lane >> 3) & 1) * 8;
                ldsm2(bfr, s2u(&smh[OFF_WFT + row * 264 + col]));
                mma16816(c2[nt], afr, bfr);
            }
        }

#pragma unroll
        for (int nt = 0; nt < 4; ++nt) {
            int colg = n0b + nt * 8 + 2 * (lane & 3);
            int r0 = m0 + (lane >> 2), r1 = r0 + 8;
            int ng0 = node0 + r0, ng1 = node0 + r1;
            if (ng0 < N) {
                float d = sDinv[r0];
                *(__half2*)&g_Fph[ng0 * 64 + colg] =
                    __floats2half2_rn(c2[nt][0] * d, c2[nt][1] * d);
            }
            if (ng1 < N) {
                float d = sDinv[r1];
                *(__half2*)&g_Fph[ng1 * 64 + colg] =
                    __floats2half2_rn(c2[nt][2] * d, c2[nt][3] * d);
            }
        }
    }
}

// ---------------- layer-2 aggregation + bias + softmax (fp16 gather) --------
__global__ void k_agg_softmax(const float* __restrict__ bf, float* __restrict__ out, int N) {
    int tid = threadIdx.x;
    int lane = tid & 15;
    int n = blockIdx.x * 16 + (tid >> 4);
    if (n >= N) return;
    const uint2* feat = (const uint2*)g_Fph;
    float4 acc = {0.f, 0.f, 0.f, 0.f};
    hadd4(acc, feat[n * 16 + lane]);                   // self-loop term
    int beg = g_off[n], end = g_off[n + 1];
    int j = beg;
    for (; j + 8 <= end; j += 8) {
        int u[8];
#pragma unroll
        for (int t = 0; t < 8; ++t) u[t] = g_csr[j + t];
        uint2 v[8];
#pragma unroll
        for (int t = 0; t < 8; ++t) v[t] = feat[u[t] * 16 + lane];
#pragma unroll
        for (int t = 0; t < 8; ++t) hadd4(acc, v[t]);
    }
    for (; j < end; ++j)
        hadd4(acc, feat[g_csr[j] * 16 + lane]);
    float s = g_dinv[n];
    float4 b4 = ((const float4*)bf)[lane];
    float4 z = {acc.x * s + b4.x, acc.y * s + b4.y,
                acc.z * s + b4.z, acc.w * s + b4.w};

    float m = fmaxf(fmaxf(z.x, z.y), fmaxf(z.z, z.w));
#pragma unroll
    for (int o = 8; o > 0; o >>= 1)
        m = fmaxf(m, __shfl_xor_sync(0xffffffffu, m, o, 16));
    z.x = __expf(z.x - m); z.y = __expf(z.y - m);
    z.z = __expf(z.z - m); z.w = __expf(z.w - m);
    float sum = z.x + z.y + z.z + z.w;
#pragma unroll
    for (int o = 8; o > 0; o >>= 1)
        sum += __shfl_xor_sync(0xffffffffu, sum, o, 16);
    float inv = 1.0f / sum;
    z.x *= inv; z.y *= inv; z.z *= inv; z.w *= inv;
    ((float4*)out)[n * 16 + lane] = z;
}

// ---------------- launch ----------------------------------------------------
extern "C" void kernel_launch(void* const* d_in, const int* in_sizes, int n_in,
                              void* d_out, int out_size) {
    const float* X  = (const float*)d_in[0];
    const void*  ei = d_in[1];            // int32 or int64 — detected on device
    const float* Wn = (const float*)d_in[3];
    const float* bn = (const float*)d_in[4];
    const float* Ws = (const float*)d_in[5];
    const float* bs = (const float*)d_in[6];
    const float* Wf = (const float*)d_in[7];
    const float* bf = (const float*)d_in[8];
    float* out = (float*)d_out;

    int N = in_sizes[0] / 64;
    int E = in_sizes[1] / 2;
    int NB = (N + 1023) / 1024;
    int NB64 = (N + 63) / 64;

    cudaFuncSetAttribute(k_aggmlp, cudaFuncAttributeMaxDynamicSharedMemorySize,
                         MLP_SMEM_BYTES);

    k_detect_zero<<<128, 1024>>>((const unsigned int*)ei, E, N);
    k_prepw<<<16, 256>>>(Wn, Ws, Wf);
    k_hist<<<(E + 511) / 512, 512>>>(ei, E, N);
    k_scan1<<<NB, 1024>>>(N);
    k_scan23<<<NB, 1024>>>(N, E);
    k_fill<<<(E + 511) / 512, 512>>>(ei, E, N);
    k_prep16<<<(N * 16 + 255) / 256, 256>>>(X, N);
    k_aggmlp<<<NB64, 256, MLP_SMEM_BYTES>>>(bn, bs, N);
    k_agg_softmax<<<(N + 15) / 16, 256>>>(bf, out, N);
}

// round 11
// speedup vs baseline: 3.6164x; 1.0790x over previous
#include <cuda_runtime.h>
#include <cuda_fp16.h>
#include <cuda_bf16.h>

// Problem constants
#define MAXN 100000
#define MAXE 1600000

typedef unsigned long long ull;
typedef unsigned int u32;

// ---------------- scratch (device globals — no runtime allocation) ----------
__device__ int    g_is64;            // 1 if ei_feat is int64, 0 if int32
__device__ int    g_cnt[MAXN];
__device__ float  g_dinv[MAXN];
__device__ int    g_off[MAXN + 1];
__device__ int    g_cur[MAXN];
__device__ int    g_csr[MAXE];
__device__ int    g_bsum[256];       // decoupled scan: block_sum+1 (0 = not ready)
__device__ __half g_Xh[MAXN * 64];   // fp16(dinv[n] * X[n])        (gather src 1)
__device__ __half g_Fph[MAXN * 64];  // fp16(dinv[n] * (H @ Wf)[n]) (gather src 2)
// pre-transposed fp16 weights, padded rows for conflict-free ldmatrix
__device__ __half g_WTa[256 * 40];   // [n(256)][k(32)+8pad]  (Wn rows 0-127, Ws 128-255)
__device__ __half g_WfT[64 * 264];   // [n(64)][k(256)+8pad]

// ---------------- helpers ---------------------------------------------------
__device__ __forceinline__ int clampN(int v, int N) {
    v = v < 0 ? 0 : v;
    return v >= N ? N - 1 : v;
}

__device__ __forceinline__ int edge_at(const void* ei, int idx) {
    return g_is64 ? ((const int*)ei)[2 * idx] : ((const int*)ei)[idx];
}

__device__ __forceinline__ float elu1(float v) {
    return v > 0.f ? v : (__expf(v) - 1.0f);
}

__device__ __forceinline__ void hadd4u(float4& a, u32 lo, u32 hi) {
    float2 f0 = __half22float2(*reinterpret_cast<__half2*>(&lo));
    float2 f1 = __half22float2(*reinterpret_cast<__half2*>(&hi));
    a.x += f0.x; a.y += f0.y; a.z += f1.x; a.w += f1.y;
}

__device__ __forceinline__ uint2 pack4h(float a, float b, float c, float d) {
    union { __half2 h[2]; uint2 u; } cv;
    cv.h[0] = __floats2half2_rn(a, b);
    cv.h[1] = __floats2half2_rn(c, d);
    return cv.u;
}

__device__ __forceinline__ u32 s2u(const void* p) {
    return (u32)__cvta_generic_to_shared(p);
}
__device__ __forceinline__ void ldsm4(u32* r, u32 a) {
    asm volatile("ldmatrix.sync.aligned.m8n8.x4.shared.b16 {%0,%1,%2,%3}, [%4];"
        : "=r"(r[0]), "=r"(r[1]), "=r"(r[2]), "=r"(r[3]) : "r"(a));
}
__device__ __forceinline__ void ldsm2(u32* r, u32 a) {
    asm volatile("ldmatrix.sync.aligned.m8n8.x2.shared.b16 {%0,%1}, [%2];"
        : "=r"(r[0]), "=r"(r[1]) : "r"(a));
}
__device__ __forceinline__ void mma16816(float* c, const u32* a, const u32* b) {
    asm volatile("mma.sync.aligned.m16n8k16.row.col.f32.f16.f16.f32 "
        "{%0,%1,%2,%3}, {%4,%5,%6,%7}, {%8,%9}, {%0,%1,%2,%3};"
        : "+f"(c[0]), "+f"(c[1]), "+f"(c[2]), "+f"(c[3])
        : "r"(a[0]), "r"(a[1]), "r"(a[2]), "r"(a[3]), "r"(b[0]), "r"(b[1]));
}

// ---------------- k_init: dtype detect + zero cnt/bsum + weight fp16 --------
__global__ void k_init(const unsigned int* __restrict__ w, int E, int N,
                       const float* __restrict__ Wn, const float* __restrict__ Ws,
                       const float* __restrict__ Wf) {
    if (blockIdx.x == 0) {
        if (threadIdx.x == 0) g_is64 = 1;
        __syncthreads();
        int npairs = E < 1024 ? E : 1024;
        if ((int)threadIdx.x < npairs) {
            if (w[2 * threadIdx.x + 1] != 0u) atomicExch(&g_is64, 0);
        }
    }
    if (blockIdx.x == 1 && threadIdx.x < 256) g_bsum[threadIdx.x] = 0;

    int stride = gridDim.x * blockDim.x;
    int gtid = blockIdx.x * blockDim.x + threadIdx.x;
    for (int i = gtid; i < N; i += stride) g_cnt[i] = 0;
    for (int idx = gtid; idx < 4096; idx += stride) {
        int k = idx >> 7, n = idx & 127;           // Wn/Ws are [32][128]
        g_WTa[n * 40 + k]         = __float2half_rn(Wn[idx]);
        g_WTa[(n + 128) * 40 + k] = __float2half_rn(Ws[idx]);
    }
    for (int idx = gtid; idx < 16384; idx += stride) {
        int k = idx >> 6, n = idx & 63;            // Wf is [256][64]
        g_WfT[n * 264 + k] = __float2half_rn(Wf[idx]);
    }
}

// ---------------- CSR build -------------------------------------------------
__global__ void k_hist(const void* __restrict__ ei, int E, int N) {
    int e = blockIdx.x * blockDim.x + threadIdx.x;
    if (e < E) {
        int dst = clampN(edge_at(ei, E + e), N);
        atomicAdd(&g_cnt[dst], 1);
    }
}

// Single-kernel scan: warp-shuffle block scan + decoupled aggregate lookback.
// All <=98 blocks are co-resident on 148 SMs (wave 1), so polling is safe.
__global__ void k_scan(int N, int E) {
    __shared__ int wsum[32];
    __shared__ int sPrefix;
    int tid = threadIdx.x, bid = blockIdx.x;
    int lane = tid & 31, wid = tid >> 5;
    int i = bid * 1024 + tid;
    int v = (i < N) ? g_cnt[i] : 0;

    // block-wide inclusive scan (shuffle)
    int incl = v;
#pragma unroll
    for (int o = 1; o < 32; o <<= 1) {
        int t = __shfl_up_sync(0xffffffffu, incl, o);
        if (lane >= o) incl += t;
    }
    if (lane == 31) wsum[wid] = incl;
    __syncthreads();
    if (wid == 0) {
        int wv = wsum[lane];
#pragma unroll
        for (int o = 1; o < 32; o <<= 1) {
            int t = __shfl_up_sync(0xffffffffu, wv, o);
            if (lane >= o) wv += t;
        }
        wsum[lane] = wv;                       // inclusive warp sums
    }
    __syncthreads();
    int incl_total = incl + (wid ? wsum[wid - 1] : 0);
    int block_sum = wsum[31];

    // publish our aggregate (value+1 so 0 == not-ready; single word => atomic)
    if (tid == 0) {
        atomicExch(&g_bsum[bid], block_sum + 1);
        sPrefix = 0;
    }
    __syncthreads();

    // lookback: poll all predecessors in parallel
    for (int b = tid; b < bid; b += 1024) {
        int vb;
        do { vb = atomicAdd(&g_bsum[b], 0); } while (vb == 0);
        atomicAdd_block(&sPrefix, vb - 1);
    }
    __syncthreads();
    int prefix = sPrefix;

    if (i < N) {
        int excl = prefix + incl_total - v;
        g_off[i] = excl;
        g_cur[i] = excl;
        g_dinv[i] = rsqrtf((float)(v + 1));
    }
    if (bid == 0 && tid == 0) g_off[N] = E;
}

__global__ void k_fill(const void* __restrict__ ei, int E, int N) {
    int e = blockIdx.x * blockDim.x + threadIdx.x;
    if (e < E) {
        int dst = clampN(edge_at(ei, E + e), N);
        int src = clampN(edge_at(ei, e), N);
        int pos = atomicAdd(&g_cur[dst], 1);
        if (pos < MAXE) g_csr[pos] = src;
    }
}

// ---------------- prep: g_Xh = fp16(dinv[n] * X[n]) -------------------------
__global__ void k_prep16(const float* __restrict__ X, int N) {
    int idx = blockIdx.x * blockDim.x + threadIdx.x;   // quad of floats
    int total = N * 16;
    if (idx < total) {
        int n = idx >> 4;
        float s = g_dinv[n];
        float4 v = ((const float4*)X)[idx];
        ((uint2*)g_Xh)[idx] = pack4h(v.x * s, v.y * s, v.z * s, v.w * s);
    }
}

// ---------------- fused agg + HMMA MLP --------------------------------------
// Layouts (halves): sXh [64][72], sWTa [256][40], sH [64][264], sWfT [64][264]
#define OFF_XH   0
#define OFF_WTA  4608
#define OFF_H    14848
#define OFF_WFT  31744
#define HALVES_TOTAL 48640
#define MLP_SMEM_BYTES (HALVES_TOTAL * 2 + 256 * 4 + 64 * 4)

__global__ __launch_bounds__(256)
void k_aggmlp(const float* __restrict__ bn, const float* __restrict__ bs, int N) {
    extern __shared__ __half smh[];
    float* sBias = (float*)(smh + HALVES_TOTAL);
    float* sDinv = sBias + 256;

    int tid = threadIdx.x;
    int node0 = blockIdx.x * 64;
    int w = tid >> 5, lane = tid & 31;

    // ---- stage weights + bias + dinv ----
    {
        const uint4* s1 = (const uint4*)g_WTa;
        uint4* d1 = (uint4*)(smh + OFF_WTA);
        for (int i = tid; i < 1280; i += 256) d1[i] = s1[i];
        const uint4* s2 = (const uint4*)g_WfT;
        uint4* d2 = (uint4*)(smh + OFF_WFT);
        for (int i = tid; i < 2112; i += 256) d2[i] = s2[i];
        sBias[tid] = (tid < 128) ? bn[tid] : bs[tid - 128];
        if (tid < 64) {
            int n = node0 + tid;
            sDinv[tid] = (n < N) ? g_dinv[n] : 0.f;
        }
    }

    // ---- Phase 0: gather-aggregate (uint4, 8 lanes/node) into sXh fp16 ----
    {
        int glane = tid & 7;             // 8 lanes per node, 8 halves each
        int nsub = tid >> 3;             // 32 nodes per pass, 2 passes
        const uint4* feat = (const uint4*)g_Xh;   // row = 8 uint4
#pragma unroll
        for (int pass = 0; pass < 2; ++pass) {
            int row = pass * 32 + nsub;
            int n = node0 + row;
            float4 a0 = {0.f, 0.f, 0.f, 0.f};
            float4 a1 = {0.f, 0.f, 0.f, 0.f};
            if (n < N) {
                uint4 sv = feat[n * 8 + glane];    // self-loop term
                hadd4u(a0, sv.x, sv.y); hadd4u(a1, sv.z, sv.w);
                int beg = g_off[n], end = g_off[n + 1];
                int j = beg;
                for (; j + 4 <= end; j += 4) {
                    int u[4];
#pragma unroll
                    for (int t = 0; t < 4; ++t) u[t] = g_csr[j + t];
                    uint4 v4[4];
#pragma unroll
                    for (int t = 0; t < 4; ++t) v4[t] = feat[u[t] * 8 + glane];
#pragma unroll
                    for (int t = 0; t < 4; ++t) {
                        hadd4u(a0, v4[t].x, v4[t].y);
                        hadd4u(a1, v4[t].z, v4[t].w);
                    }
                }
                for (; j < end; ++j) {
                    uint4 vv = feat[g_csr[j] * 8 + glane];
                    hadd4u(a0, vv.x, vv.y); hadd4u(a1, vv.z, vv.w);
                }
                float dn = g_dinv[n];
                a0.x *= dn; a0.y *= dn; a0.z *= dn; a0.w *= dn;
                a1.x *= dn; a1.y *= dn; a1.z *= dn; a1.w *= dn;
            }
            uint2 p0 = pack4h(a0.x, a0.y, a0.z, a0.w);
            uint2 p1 = pack4h(a1.x, a1.y, a1.z, a1.w);
            *(uint4*)&smh[OFF_XH + row * 72 + glane * 8] =
                make_uint4(p0.x, p0.y, p1.x, p1.y);
        }
    }
    __syncthreads();

    // ---- Phase A: H[64][256] = elu(Xt @ blockdiag(Wn,Ws) + b), warp = 32 cols
    {
        int hsel = w >> 2;              // warps 0-3: cols 0-127 (nuc), 4-7: surf
        int n0w = w * 32;               // global col base
        float c[4][4][4];
#pragma unroll
        for (int mt = 0; mt < 4; ++mt)
#pragma unroll
            for (int nt = 0; nt < 4; ++nt)
#pragma unroll
                for (int i = 0; i < 4; ++i) c[mt][nt][i] = 0.f;

        u32 bfr[4][2][2];
#pragma unroll
        for (int nt = 0; nt < 4; ++nt)
#pragma unroll
            for (int ks = 0; ks < 2; ++ks) {
                int row = n0w + nt * 8 + (lane & 7);
                int col = ks * 16 + ((lane >> 3) & 1) * 8;
                ldsm2(bfr[nt][ks], s2u(&smh[OFF_WTA + row * 40 + col]));
            }

#pragma unroll
        for (int mt = 0; mt < 4; ++mt) {
            u32 afr[2][4];
#pragma unroll
            for (int ks = 0; ks < 2; ++ks) {
                int row = mt * 16 + (lane & 15);
                int col = hsel * 32 + ks * 16 + (lane >> 4) * 8;
                ldsm4(afr[ks], s2u(&smh[OFF_XH + row * 72 + col]));
            }
#pragma unroll
            for (int nt = 0; nt < 4; ++nt) {
                mma16816(c[mt][nt], afr[0], bfr[nt][0]);
                mma16816(c[mt][nt], afr[1], bfr[nt][1]);
            }
        }

        // epilogue: bias + elu -> sH fp16
#pragma unroll
        for (int mt = 0; mt < 4; ++mt)
#pragma unroll
            for (int nt = 0; nt < 4; ++nt) {
                int colg = n0w + nt * 8 + 2 * (lane & 3);
                float b0 = sBias[colg], b1 = sBias[colg + 1];
                int r0 = mt * 16 + (lane >> 2);
                *(__half2*)&smh[OFF_H + r0 * 264 + colg] =
                    __floats2half2_rn(elu1(c[mt][nt][0] + b0), elu1(c[mt][nt][1] + b1));
                *(__half2*)&smh[OFF_H + (r0 + 8) * 264 + colg] =
                    __floats2half2_rn(elu1(c[mt][nt][2] + b0), elu1(c[mt][nt][3] + b1));
            }
    }
    __syncthreads();

    // ---- Phase B: Fp[64][64] = dinv * (H @ Wf), warp tile 16x32, K=256 ----
    {
        int m0 = (w & 3) * 16, n0b = (w >> 2) * 32;
        float c2[4][4];
#pragma unroll
        for (int nt = 0; nt < 4; ++nt)
#pragma unroll
            for (int i = 0; i < 4; ++i) c2[nt][i] = 0.f;

        for (int ks = 0; ks < 16; ++ks) {
            int k0 = ks * 16;
            u32 afr[4];
            {
                int row = m0 + (lane & 15);
                int col = k0 + (lane >> 4) * 8;
                ldsm4(afr, s2u(&smh[OFF_H + row * 264 + col]));
            }
#pragma unroll
            for (int nt = 0; nt < 4; ++nt) {
                u32 bfr[2];
                int row = n0b + nt * 8 + (lane & 7);
                int col = k0 + ((lane >> 3) & 1) * 8;
                ldsm2(bfr, s2u(&smh[OFF_WFT + row * 264 + col]));
                mma16816(c2[nt], afr, bfr);
            }
        }

#pragma unroll
        for (int nt = 0; nt < 4; ++nt) {
            int colg = n0b + nt * 8 + 2 * (lane & 3);
            int r0 = m0 + (lane >> 2), r1 = r0 + 8;
            int ng0 = node0 + r0, ng1 = node0 + r1;
            if (ng0 < N) {
                float d = sDinv[r0];
                *(__half2*)&g_Fph[ng0 * 64 + colg] =
                    __floats2half2_rn(c2[nt][0] * d, c2[nt][1] * d);
            }
            if (ng1 < N) {
                float d = sDinv[r1];
                *(__half2*)&g_Fph[ng1 * 64 + colg] =
                    __floats2half2_rn(c2[nt][2] * d, c2[nt][3] * d);
            }
        }
    }
}

// ---------------- layer-2 aggregation + bias + softmax (uint4 gather) -------
__global__ void k_agg_softmax(const float* __restrict__ bf, float* __restrict__ out, int N) {
    int tid = threadIdx.x;
    int glane = tid & 7;                 // 8 lanes per node, 8 logits each
    int n = blockIdx.x * 32 + (tid >> 3);
    if (n >= N) return;
    const uint4* feat = (const uint4*)g_Fph;
    float4 a0 = {0.f, 0.f, 0.f, 0.f};
    float4 a1 = {0.f, 0.f, 0.f, 0.f};
    {
        uint4 sv = feat[n * 8 + glane];  // self-loop term
        hadd4u(a0, sv.x, sv.y); hadd4u(a1, sv.z, sv.w);
    }
    int beg = g_off[n], end = g_off[n + 1];
    int j = beg;
    for (; j + 4 <= end; j += 4) {
        int u[4];
#pragma unroll
        for (int t = 0; t < 4; ++t) u[t] = g_csr[j + t];
        uint4 v4[4];
#pragma unroll
        for (int t = 0; t < 4; ++t) v4[t] = feat[u[t] * 8 + glane];
#pragma unroll
        for (int t = 0; t < 4; ++t) {
            hadd4u(a0, v4[t].x, v4[t].y);
            hadd4u(a1, v4[t].z, v4[t].w);
        }
    }
    for (; j < end; ++j) {
        uint4 vv = feat[g_csr[j] * 8 + glane];
        hadd4u(a0, vv.x, vv.y); hadd4u(a1, vv.z, vv.w);
    }
    float s = g_dinv[n];
    float4 b0 = ((const float4*)bf)[glane * 2];
    float4 b1 = ((const float4*)bf)[glane * 2 + 1];
    float4 z0 = {a0.x * s + b0.x, a0.y * s + b0.y, a0.z * s + b0.z, a0.w * s + b0.w};
    float4 z1 = {a1.x * s + b1.x, a1.y * s + b1.y, a1.z * s + b1.z, a1.w * s + b1.w};

    // softmax over 64 logits spread across 8 lanes (8 each)
    float m = fmaxf(fmaxf(fmaxf(z0.x, z0.y), fmaxf(z0.z, z0.w)),
                    fmaxf(fmaxf(z1.x, z1.y), fmaxf(z1.z, z1.w)));
#pragma unroll
    for (int o = 4; o > 0; o >>= 1)
        m = fmaxf(m, __shfl_xor_sync(0xffffffffu, m, o, 8));
    z0.x = __expf(z0.x - m); z0.y = __expf(z0.y - m);
    z0.z = __expf(z0.z - m); z0.w = __expf(z0.w - m);
    z1.x = __expf(z1.x - m); z1.y = __expf(z1.y - m);
    z1.z = __expf(z1.z - m); z1.w = __expf(z1.w - m);
    float sum = z0.x + z0.y + z0.z + z0.w + z1.x + z1.y + z1.z + z1.w;
#pragma unroll
    for (int o = 4; o > 0; o >>= 1)
        sum += __shfl_xor_sync(0xffffffffu, sum, o, 8);
    float inv = 1.0f / sum;
    z0.x *= inv; z0.y *= inv; z0.z *= inv; z0.w *= inv;
    z1.x *= inv; z1.y *= inv; z1.z *= inv; z1.w *= inv;
    ((float4*)out)[n * 16 + glane * 2]     = z0;
    ((float4*)out)[n * 16 + glane * 2 + 1] = z1;
}

// ---------------- launch ----------------------------------------------------
extern "C" void kernel_launch(void* const* d_in, const int* in_sizes, int n_in,
                              void* d_out, int out_size) {
    const float* X  = (const float*)d_in[0];
    const void*  ei = d_in[1];            // int32 or int64 — detected on device
    const float* Wn = (const float*)d_in[3];
    const float* bn = (const float*)d_in[4];
    const float* Ws = (const float*)d_in[5];
    const float* bs = (const float*)d_in[6];
    const float* Wf = (const float*)d_in[7];
    const float* bf = (const float*)d_in[8];
    float* out = (float*)d_out;

    int N = in_sizes[0] / 64;
    int E = in_sizes[1] / 2;
    int NB = (N + 1023) / 1024;
    int NB64 = (N + 63) / 64;

    cudaFuncSetAttribute(k_aggmlp, cudaFuncAttributeMaxDynamicSharedMemorySize,
                         MLP_SMEM_BYTES);

    k_init<<<128, 1024>>>((const unsigned int*)ei, E, N, Wn, Ws, Wf);
    k_hist<<<(E + 511) / 512, 512>>>(ei, E, N);
    k_scan<<<NB, 1024>>>(N, E);
    k_fill<<<(E + 511) / 512, 512>>>(ei, E, N);
    k_prep16<<<(N * 16 + 255) / 256, 256>>>(X, N);
    k_aggmlp<<<NB64, 256, MLP_SMEM_BYTES>>>(bn, bs, N);
    k_agg_softmax<<<(N + 31) / 32, 256>>>(bf, out, N);
}